// round 10
// baseline (speedup 1.0000x reference)
#include <cuda_runtime.h>
#include <cuda_bf16.h>
#include <math.h>
#include <stdint.h>

// Problem constants
#define SQ   4096
#define EMB  768
#define NH   12
#define HD   64
#define WIN  256
#define K2   2304   // 3 * 768 split-GEMM depth

// Scratch (allocation-free rule: __device__ globals)
__device__ float g_q[NH * SQ * HD];
__device__ float g_k[NH * SQ * HD];
__device__ float g_v[NH * SQ * HD];
__device__ __align__(16) __nv_bfloat16 g_as[(size_t)SQ * K2];        // A' [4096][2304] slabs [hi,hi,lo]
__device__ __align__(16) __nv_bfloat16 g_bs[(size_t)3 * EMB * K2];   // B'_z [768 n][2304 k] slabs [hi,lo,hi]

// ---------------------------------------------------------------------------
// PTX helpers — tcgen05 only under the sm_103a feature guard.
// ---------------------------------------------------------------------------
__device__ __forceinline__ uint32_t smem_u32(const void* p) {
    uint32_t a;
    asm("{ .reg .u64 t; cvta.to.shared.u64 t, %1; cvt.u32.u64 %0, t; }" : "=r"(a) : "l"(p));
    return a;
}
__device__ __forceinline__ uint32_t elect_one() {
    uint32_t pred;
    asm volatile("{\n\t.reg .pred p;\n\telect.sync _|p, 0xFFFFFFFF;\n\tselp.b32 %0, 1, 0, p;\n\t}" : "=r"(pred));
    return pred;
}
__device__ __forceinline__ void mbar_init(uint32_t mb, uint32_t cnt) {
    asm volatile("mbarrier.init.shared.b64 [%0], %1;" :: "r"(mb), "r"(cnt) : "memory");
}
__device__ __forceinline__ void mbar_wait(uint32_t mb, uint32_t phase) {
    asm volatile(
        "{\n\t.reg .pred P1;\n\t"
        "WL_%=:\n\t"
        "mbarrier.try_wait.parity.acquire.cta.shared::cta.b64 P1, [%0], %1, 0x989680;\n\t"
        "@P1 bra.uni WD_%=;\n\t"
        "bra.uni WL_%=;\n\t"
        "WD_%=:\n\t}"
        :: "r"(mb), "r"(phase) : "memory");
}

#if defined(__CUDA_ARCH_FEAT_SM103_ALL)
#define TC_OK 1
#else
#define TC_OK 0
#endif

#if TC_OK
__device__ __forceinline__ void mma_f16_ss(uint32_t d, uint64_t a, uint64_t b,
                                           uint32_t idesc, bool acc) {
    uint32_t en = acc ? 1u : 0u;
    asm volatile(
        "{\n\t.reg .pred p;\n\tsetp.ne.u32 p, %5, 0;\n\t"
        "tcgen05.mma.cta_group::1.kind::f16 [%0], %1, %2, %3, {%4, %4, %4, %4}, p;\n\t}"
        :: "r"(d), "l"(a), "l"(b), "r"(idesc), "r"(0u), "r"(en) : "memory");
}
__device__ __forceinline__ void tc_commit(uint32_t mb) {
    asm volatile("tcgen05.commit.cta_group::1.mbarrier::arrive::one.shared::cluster.b64 [%0];"
                 :: "r"(mb) : "memory");
}
#define TC_LD_X32(r, addr) \
    asm volatile( \
        "tcgen05.ld.sync.aligned.32x32b.x32.b32 " \
        "{%0, %1, %2, %3, %4, %5, %6, %7, " \
        " %8, %9, %10, %11, %12, %13, %14, %15, " \
        " %16, %17, %18, %19, %20, %21, %22, %23, " \
        " %24, %25, %26, %27, %28, %29, %30, %31}, [%32];" \
        : "=r"((r)[0]),  "=r"((r)[1]),  "=r"((r)[2]),  "=r"((r)[3]), \
          "=r"((r)[4]),  "=r"((r)[5]),  "=r"((r)[6]),  "=r"((r)[7]), \
          "=r"((r)[8]),  "=r"((r)[9]),  "=r"((r)[10]), "=r"((r)[11]), \
          "=r"((r)[12]), "=r"((r)[13]), "=r"((r)[14]), "=r"((r)[15]), \
          "=r"((r)[16]), "=r"((r)[17]), "=r"((r)[18]), "=r"((r)[19]), \
          "=r"((r)[20]), "=r"((r)[21]), "=r"((r)[22]), "=r"((r)[23]), \
          "=r"((r)[24]), "=r"((r)[25]), "=r"((r)[26]), "=r"((r)[27]), \
          "=r"((r)[28]), "=r"((r)[29]), "=r"((r)[30]), "=r"((r)[31]) \
        : "r"(addr))
#endif

static __device__ __forceinline__ uint64_t make_desc(uint32_t addr) {
    const uint64_t base = (2ull << 61) | (1ull << 46) | (64ull << 32) | (1ull << 16);
    return base | ((uint64_t)(addr >> 4) & 0x3FFF);
}
static __device__ __forceinline__ uint32_t sw128(uint32_t off) {
    return off ^ ((off >> 3) & 0x70);
}
static __device__ __forceinline__ uint32_t pack_bf2(float a, float b) {
    __nv_bfloat162 t = __floats2bfloat162_rn(a, b);
    return *(uint32_t*)&t;
}

// ---------------------------------------------------------------------------
// Split pre-pass: hs -> g_as (slabs hi,hi,lo)
// ---------------------------------------------------------------------------
__global__ void split_hs_kernel(const float* __restrict__ hs)
{
    int i = blockIdx.x * 256 + threadIdx.x;
    float x = hs[i];
    __nv_bfloat16 h = __float2bfloat16(x);
    __nv_bfloat16 l = __float2bfloat16(x - __bfloat162float(h));
    int row = i / EMB, k = i - row * EMB;
    __nv_bfloat16* p = &g_as[(size_t)row * K2];
    p[k] = h; p[EMB + k] = h; p[2 * EMB + k] = l;
}

__global__ void split_w_kernel(const float* __restrict__ Wq,
                               const float* __restrict__ Wk,
                               const float* __restrict__ Wv)
{
    __shared__ float t[32][33];
    const int z = blockIdx.z;
    const float* W = (z == 0) ? Wq : (z == 1) ? Wk : Wv;
    int k = blockIdx.y * 32 + threadIdx.y;
    int n = blockIdx.x * 32 + threadIdx.x;
    t[threadIdx.y][threadIdx.x] = W[(size_t)k * EMB + n];
    __syncthreads();
    int nn = blockIdx.x * 32 + threadIdx.y;
    int kk = blockIdx.y * 32 + threadIdx.x;
    float x = t[threadIdx.x][threadIdx.y];
    __nv_bfloat16 h = __float2bfloat16(x);
    __nv_bfloat16 l = __float2bfloat16(x - __bfloat162float(h));
    __nv_bfloat16* p = &g_bs[((size_t)z * EMB + nn) * K2];
    p[kk] = h; p[EMB + kk] = l; p[2 * EMB + kk] = h;
}

// ---------------------------------------------------------------------------
// QKV GEMM on tcgen05 (validated R6/R7, unchanged).
// ---------------------------------------------------------------------------
#define STAGE_BYTES 49152
#define QKV_SMEM (2 * STAGE_BYTES + 32)
#define QKV_IDESC 0x8400490u

__global__ __launch_bounds__(256) void qkv_mma_kernel(
    const float* __restrict__ bq, const float* __restrict__ bk,
    const float* __restrict__ bv)
{
    const int z = blockIdx.z;
    const float* bias = (z == 0) ? bq : (z == 1) ? bk : bv;
    float* dst = (z == 0) ? g_q : (z == 1) ? g_k : g_v;
    const int n0 = blockIdx.x * 256;
    const int m0 = blockIdx.y * 128;
    const int tid = threadIdx.x;

#if TC_OK
    extern __shared__ __align__(1024) char sm[];
    const uint32_t sb = smem_u32(sm);
    const int wid = tid >> 5, lid = tid & 31;

    const uint32_t ctrl = sb + 2 * STAGE_BYTES;
    const uint32_t mb[2] = { sb + 2 * STAGE_BYTES + 8, sb + 2 * STAGE_BYTES + 16 };

    if (tid == 0) { mbar_init(mb[0], 1); mbar_init(mb[1], 1); }
    if (wid == 0) {
        asm volatile("tcgen05.alloc.cta_group::1.sync.aligned.shared::cta.b32 [%0], %1;"
                     :: "r"(ctrl), "r"(256u) : "memory");
        asm volatile("tcgen05.relinquish_alloc_permit.cta_group::1.sync.aligned;");
    }
    __syncthreads();
    uint32_t tmem;
    asm volatile("ld.shared.b32 %0, [%1];" : "=r"(tmem) : "r"(ctrl));

    const __nv_bfloat16* Arow = &g_as[(size_t)m0 * K2];
    const __nv_bfloat16* Brow = &g_bs[((size_t)z * EMB + n0) * K2];

    int ph[2] = { 0, 0 };

    for (int c = 0; c < 36; c++) {
        const int s = c & 1;
        if (c >= 2) { mbar_wait(mb[s], ph[s]); ph[s] ^= 1; }
        const int kk = c * 64;
        char* stA = sm + s * STAGE_BYTES;
        char* stB = stA + 16384;

        #pragma unroll
        for (int j = 0; j < 4; j++) {
            int cid = tid + j * 256;
            int r = cid >> 3, c16 = cid & 7;
            uint32_t off = sw128((uint32_t)(r * 128 + c16 * 16));
            *(uint4*)(stA + off) = *(const uint4*)(Arow + (size_t)r * K2 + kk + c16 * 8);
        }
        #pragma unroll
        for (int j = 0; j < 8; j++) {
            int cid = tid + j * 256;
            int r = cid >> 3, c16 = cid & 7;
            uint32_t off = sw128((uint32_t)(r * 128 + c16 * 16));
            *(uint4*)(stB + off) = *(const uint4*)(Brow + (size_t)r * K2 + kk + c16 * 8);
        }
        asm volatile("fence.proxy.async.shared::cta;" ::: "memory");
        __syncthreads();

        if (wid == 0) {
            if (elect_one()) {
                uint64_t da = make_desc(sb + s * STAGE_BYTES);
                uint64_t db = make_desc(sb + s * STAGE_BYTES + 16384);
                #pragma unroll
                for (int k = 0; k < 4; k++)
                    mma_f16_ss(tmem, da + k * 2, db + k * 2, QKV_IDESC, (c > 0) || (k > 0));
                tc_commit(mb[s]);
            }
        }
    }

    mbar_wait(mb[1], ph[1]);
    asm volatile("tcgen05.fence::after_thread_sync;" ::: "memory");

    if (wid < 4) {
        const int r = wid * 32 + lid;
        const float scl = (z == 0) ? 0.125f : 1.0f;
        #pragma unroll
        for (int cb = 0; cb < 8; cb++) {
            uint32_t dr[32];
            TC_LD_X32(dr, tmem + cb * 32);
            asm volatile("tcgen05.wait::ld.sync.aligned;" ::: "memory");
            const int nbase = n0 + cb * 32;
            const int head = nbase >> 6;
            float* op = &dst[((size_t)head * SQ + m0 + r) * HD + (nbase & 63)];
            #pragma unroll
            for (int q = 0; q < 32; q += 4) {
                float4 v;
                v.x = (__uint_as_float(dr[q + 0]) + bias[nbase + q + 0]) * scl;
                v.y = (__uint_as_float(dr[q + 1]) + bias[nbase + q + 1]) * scl;
                v.z = (__uint_as_float(dr[q + 2]) + bias[nbase + q + 2]) * scl;
                v.w = (__uint_as_float(dr[q + 3]) + bias[nbase + q + 3]) * scl;
                *(float4*)&op[q] = v;
            }
        }
    }
    __syncthreads();
    if (wid == 0) {
        asm volatile("tcgen05.dealloc.cta_group::1.sync.aligned.b32 %0, %1;"
                     :: "r"(tmem), "r"(256u));
    }
#else
    const int r = tid >> 1;
    const int cb0 = (tid & 1) * 128;
    const float scl = (z == 0) ? 0.125f : 1.0f;
    const __nv_bfloat16* a = &g_as[(size_t)(m0 + r) * K2];
    for (int cc = 0; cc < 128; cc++) {
        const int n = n0 + cb0 + cc;
        const __nv_bfloat16* b = &g_bs[((size_t)z * EMB + n) * K2];
        float acc = 0.0f;
        for (int k = 0; k < K2; k++)
            acc += __bfloat162float(a[k]) * __bfloat162float(b[k]);
        const int head = n >> 6;
        dst[((size_t)head * SQ + m0 + r) * HD + (n & 63)] = (acc + bias[n]) * scl;
    }
#endif
}

// ---------------------------------------------------------------------------
// Banded attention on tcgen05, software-pipelined, no-max softmax.
// Per CTA = (head, 128 queries), block = 128.
// TMEM: S0 @0, S1 @64, O @128 (alloc 256). smem: K/Vt double-buffered.
// DEADLOCK FIX vs R8: per-buffer S barriers (mbS0/mbS1) — a single shared
// barrier could flip parity twice before the waiters polled (ABA) and hang.
// ---------------------------------------------------------------------------
#define AT_QHI   0          // 16KB  (128 x 128B)
#define AT_QLO   16384
#define AT_KB0   32768      // per buffer: KHI +0 (8KB), KLO +8192, VTHI +16384, VTLO +24576
#define AT_KBSZ  32768
#define AT_PHI   98304      // 16KB
#define AT_PLO   114688     // 16KB
#define AT_VSTG  131072     // fp32 [64][65] = 16640B
#define AT_KMSK  147712     // 2 x 64 floats
#define AT_CTRL  148224
#define AT_MBS0  148232
#define AT_MBS1  148240
#define AT_MBO   148248
#define AT_SMEM  148288
#define ATT_IDESC 0x8100490u   // f32 acc, bf16 a/b, N=64, M=128

__global__ __launch_bounds__(128) void attn_mma_kernel(
    const float* __restrict__ amask,
    const unsigned char* __restrict__ qmask,
    float* __restrict__ out)
{
    const int h  = blockIdx.y;
    const int q0 = blockIdx.x * 128;
    const int tid = threadIdx.x;

#if TC_OK
    extern __shared__ __align__(1024) char sm[];
    const uint32_t sb = smem_u32(sm);
    const int wid = tid >> 5;
    const uint32_t mbS[2] = { sb + AT_MBS0, sb + AT_MBS1 };
    const uint32_t mbO = sb + AT_MBO;
    float* kmsk = (float*)(sm + AT_KMSK);
    float* vstg = (float*)(sm + AT_VSTG);

    if (tid == 0) { mbar_init(mbS[0], 1); mbar_init(mbS[1], 1); mbar_init(mbO, 1); }
    if (wid == 0) {
        asm volatile("tcgen05.alloc.cta_group::1.sync.aligned.shared::cta.b32 [%0], %1;"
                     :: "r"(sb + AT_CTRL), "r"(256u) : "memory");
        asm volatile("tcgen05.relinquish_alloc_permit.cta_group::1.sync.aligned;");
    }
    __syncthreads();
    uint32_t tmem;
    asm volatile("ld.shared.b32 %0, [%1];" : "=r"(tmem) : "r"(sb + AT_CTRL));
    const uint32_t TM_O = tmem + 128;

    // valid band tiles
    int jbs[10]; int nt = 0;
    #pragma unroll
    for (int t = 0; t < 10; t++) {
        int jb = q0 - 256 + t * 64;
        if (jb >= 0 && jb < SQ) jbs[nt++] = jb;
    }

    const int gi = q0 + tid;

    // ---- Prologue: Q tile -> Qhi/Qlo bf16 swizzled ----
    {
        const float* qp = &g_q[((size_t)h * SQ + gi) * HD];
        float f[64];
        #pragma unroll
        for (int i = 0; i < 16; i++) *(float4*)&f[i * 4] = *(const float4*)&qp[i * 4];
        #pragma unroll
        for (int g = 0; g < 8; g++) {
            uint32_t off = sw128((uint32_t)(tid * 128 + g * 16));
            uint4 hv, lv;
            #pragma unroll
            for (int e = 0; e < 8; e += 2) {
                float x0 = f[g * 8 + e], x1 = f[g * 8 + e + 1];
                float h0 = __bfloat162float(__float2bfloat16(x0));
                float h1 = __bfloat162float(__float2bfloat16(x1));
                ((uint32_t*)&hv)[e >> 1] = pack_bf2(h0, h1);
                ((uint32_t*)&lv)[e >> 1] = pack_bf2(x0 - h0, x1 - h1);
            }
            *(uint4*)(sm + AT_QHI + off) = hv;
            *(uint4*)(sm + AT_QLO + off) = lv;
        }
    }

    // stage A: load K tile into Khi/Klo of buffer b; V tile into vstg; kmsk[b]
    auto stage_load = [&](int jb, int b) {
        const int rk = tid >> 1, half = (tid & 1) * 32;
        char* kb = sm + AT_KB0 + b * AT_KBSZ;
        const float* kp = &g_k[((size_t)h * SQ + jb + rk) * HD + half];
        const float* vp = &g_v[((size_t)h * SQ + jb + rk) * HD + half];
        float f[32];
        #pragma unroll
        for (int i = 0; i < 8; i++) *(float4*)&f[i * 4] = *(const float4*)&kp[i * 4];
        #pragma unroll
        for (int g = 0; g < 4; g++) {
            uint32_t off = sw128((uint32_t)(rk * 128 + half * 2 + g * 16));
            uint4 hv, lv;
            #pragma unroll
            for (int e = 0; e < 8; e += 2) {
                float x0 = f[g * 8 + e], x1 = f[g * 8 + e + 1];
                float h0 = __bfloat162float(__float2bfloat16(x0));
                float h1 = __bfloat162float(__float2bfloat16(x1));
                ((uint32_t*)&hv)[e >> 1] = pack_bf2(h0, h1);
                ((uint32_t*)&lv)[e >> 1] = pack_bf2(x0 - h0, x1 - h1);
            }
            *(uint4*)(kb + off) = hv;
            *(uint4*)(kb + 8192 + off) = lv;
        }
        #pragma unroll
        for (int i = 0; i < 32; i++) vstg[rk * 65 + half + i] = vp[i];
        if (tid < 64)
            kmsk[b * 64 + tid] = (amask[jb + tid] != 0.0f) ? -1e8f : 0.0f;
    };

    // stage B: transpose vstg -> Vthi/Vtlo of buffer b
    auto stage_vt = [&](int b) {
        char* kb = sm + AT_KB0 + b * AT_KBSZ;
        const int d = tid & 63, kh = (tid >> 6) * 32;
        float f[32];
        #pragma unroll
        for (int i = 0; i < 32; i++) f[i] = vstg[(kh + i) * 65 + d];
        #pragma unroll
        for (int g = 0; g < 4; g++) {
            uint32_t off = sw128((uint32_t)(d * 128 + kh * 2 + g * 16));
            uint4 hv, lv;
            #pragma unroll
            for (int e = 0; e < 8; e += 2) {
                float x0 = f[g * 8 + e], x1 = f[g * 8 + e + 1];
                float h0 = __bfloat162float(__float2bfloat16(x0));
                float h1 = __bfloat162float(__float2bfloat16(x1));
                ((uint32_t*)&hv)[e >> 1] = pack_bf2(h0, h1);
                ((uint32_t*)&lv)[e >> 1] = pack_bf2(x0 - h0, x1 - h1);
            }
            *(uint4*)(kb + 16384 + off) = hv;
            *(uint4*)(kb + 24576 + off) = lv;
        }
    };

    const uint64_t dQh = make_desc(sb + AT_QHI), dQl = make_desc(sb + AT_QLO);
    const uint64_t dPh = make_desc(sb + AT_PHI), dPl = make_desc(sb + AT_PLO);

    auto issue_S = [&](int b) {   // S(buf b) = Q.K^T, 3-term split -> commit mbS[b]
        uint32_t kbase = sb + AT_KB0 + b * AT_KBSZ;
        uint64_t dKh = make_desc(kbase), dKl = make_desc(kbase + 8192);
        uint32_t d = tmem + b * 64;
        asm volatile("tcgen05.fence::after_thread_sync;" ::: "memory");
        #pragma unroll
        for (int k = 0; k < 4; k++) mma_f16_ss(d, dQh + k * 2, dKh + k * 2, ATT_IDESC, k > 0);
        #pragma unroll
        for (int k = 0; k < 4; k++) mma_f16_ss(d, dQh + k * 2, dKl + k * 2, ATT_IDESC, true);
        #pragma unroll
        for (int k = 0; k < 4; k++) mma_f16_ss(d, dQl + k * 2, dKh + k * 2, ATT_IDESC, true);
        tc_commit(mbS[b]);
    };

    float l_i = 0.0f;
    int phS[2] = { 0, 0 };
    int phO = 0;

    // ---- Prologue: stage tile 0, issue S(0) ----
    stage_load(jbs[0], 0);
    __syncthreads();
    stage_vt(0);
    asm volatile("fence.proxy.async.shared::cta;" ::: "memory");
    __syncthreads();
    if (wid == 0 && elect_one()) issue_S(0);

    for (int it = 0; it < nt; it++) {
        const int b = it & 1, nb = b ^ 1;
        const bool more = (it + 1 < nt);
        const int jb = jbs[it];

        // stage next tile's K + V(stage) + kmsk (global-load heavy: hides mbO wait)
        if (more) stage_load(jbs[it + 1], nb);

        // PV(it-1) must complete before we overwrite Vt(nb) and P
        if (it > 0) { mbar_wait(mbO, phO); phO ^= 1; }

        if (more) {
            __syncthreads();          // vstg writes visible
            stage_vt(nb);
        }
        asm volatile("fence.proxy.async.shared::cta;" ::: "memory");
        __syncthreads();
        if (more && wid == 0 && elect_one()) issue_S(nb);

        // wait S(it) — per-buffer barrier, exactly one outstanding commit
        mbar_wait(mbS[b], phS[b]); phS[b] ^= 1;
        asm volatile("tcgen05.fence::after_thread_sync;" ::: "memory");

        // softmax (no max subtraction; thread-local row)
        uint32_t s0[32], s1[32];
        TC_LD_X32(s0, tmem + b * 64);
        TC_LD_X32(s1, tmem + b * 64 + 32);
        asm volatile("tcgen05.wait::ld.sync.aligned;" ::: "memory");
        asm volatile("tcgen05.fence::before_thread_sync;" ::: "memory");

        float p[64];
        float rs = 0.0f;
        #pragma unroll
        for (int j = 0; j < 64; j++) {
            const int diff = gi - (jb + j);
            const bool valid = (diff <= WIN) && (diff >= -WIN);
            float sv = __uint_as_float(j < 32 ? s0[j] : s1[j - 32]) + kmsk[b * 64 + j];
            float pv = valid ? __expf(sv) : 0.0f;
            p[j] = pv;
            rs += pv;
        }
        l_i += rs;

        // store P hi/lo
        #pragma unroll
        for (int g = 0; g < 8; g++) {
            uint32_t off = sw128((uint32_t)(tid * 128 + g * 16));
            uint4 hv, lv;
            #pragma unroll
            for (int e = 0; e < 8; e += 2) {
                float x0 = p[g * 8 + e], x1 = p[g * 8 + e + 1];
                float h0 = __bfloat162float(__float2bfloat16(x0));
                float h1 = __bfloat162float(__float2bfloat16(x1));
                ((uint32_t*)&hv)[e >> 1] = pack_bf2(h0, h1);
                ((uint32_t*)&lv)[e >> 1] = pack_bf2(x0 - h0, x1 - h1);
            }
            *(uint4*)(sm + AT_PHI + off) = hv;
            *(uint4*)(sm + AT_PLO + off) = lv;
        }
        asm volatile("fence.proxy.async.shared::cta;" ::: "memory");
        __syncthreads();

        // O += P.V (3-term split)
        if (wid == 0 && elect_one()) {
            uint32_t kbase = sb + AT_KB0 + b * AT_KBSZ;
            uint64_t dVh = make_desc(kbase + 16384), dVl = make_desc(kbase + 24576);
            asm volatile("tcgen05.fence::after_thread_sync;" ::: "memory");
            #pragma unroll
            for (int k = 0; k < 4; k++) mma_f16_ss(TM_O, dPh + k * 2, dVh + k * 2, ATT_IDESC, !(it == 0 && k == 0));
            #pragma unroll
            for (int k = 0; k < 4; k++) mma_f16_ss(TM_O, dPh + k * 2, dVl + k * 2, ATT_IDESC, true);
            #pragma unroll
            for (int k = 0; k < 4; k++) mma_f16_ss(TM_O, dPl + k * 2, dVh + k * 2, ATT_IDESC, true);
            tc_commit(mbO);
        }
    }

    // ---- Epilogue ----
    mbar_wait(mbO, phO);
    asm volatile("tcgen05.fence::after_thread_sync;" ::: "memory");
    {
        uint32_t o0[32], o1[32];
        TC_LD_X32(o0, TM_O);
        TC_LD_X32(o1, TM_O + 32);
        asm volatile("tcgen05.wait::ld.sync.aligned;" ::: "memory");
        const float inv = (qmask[gi] != 0) ? 0.0f : 1.0f / l_i;
        float* op = &out[(size_t)gi * EMB + h * HD];
        #pragma unroll
        for (int j = 0; j < 32; j += 4) {
            float4 v;
            v.x = __uint_as_float(o0[j + 0]) * inv;
            v.y = __uint_as_float(o0[j + 1]) * inv;
            v.z = __uint_as_float(o0[j + 2]) * inv;
            v.w = __uint_as_float(o0[j + 3]) * inv;
            *(float4*)&op[j] = v;
            v.x = __uint_as_float(o1[j + 0]) * inv;
            v.y = __uint_as_float(o1[j + 1]) * inv;
            v.z = __uint_as_float(o1[j + 2]) * inv;
            v.w = __uint_as_float(o1[j + 3]) * inv;
            *(float4*)&op[32 + j] = v;
        }
    }
    __syncthreads();
    if (wid == 0) {
        asm volatile("tcgen05.dealloc.cta_group::1.sync.aligned.b32 %0, %1;"
                     :: "r"(tmem), "r"(256u));
    }
#else
    // Generic fallback (compute_103 PTX pass only; never runs on GB300).
    const int gi = q0 + tid;
    const float* qp = &g_q[((size_t)h * SQ + gi) * HD];
    float l = 0.0f, O[64];
    #pragma unroll
    for (int d = 0; d < 64; d++) O[d] = 0.0f;
    int lo = gi - WIN; if (lo < 0) lo = 0;
    int hi = gi + WIN; if (hi > SQ - 1) hi = SQ - 1;
    for (int gj = lo; gj <= hi; gj++) {
        const float* kp = &g_k[((size_t)h * SQ + gj) * HD];
        float s = 0.0f;
        for (int d = 0; d < 64; d++) s += qp[d] * kp[d];
        s += (amask[gj] != 0.0f) ? -1e8f : 0.0f;
        float pv = __expf(s);
        l += pv;
        const float* vp = &g_v[((size_t)h * SQ + gj) * HD];
        for (int d = 0; d < 64; d++) O[d] += pv * vp[d];
    }
    const float inv = (qmask[gi] != 0) ? 0.0f : 1.0f / l;
    float* op = &out[(size_t)gi * EMB + h * HD];
    for (int d = 0; d < 64; d++) op[d] = O[d] * inv;
#endif
}

// ---------------------------------------------------------------------------
// Launch
// ---------------------------------------------------------------------------
extern "C" void kernel_launch(void* const* d_in, const int* in_sizes, int n_in,
                              void* d_out, int out_size)
{
    const float* hs            = (const float*)d_in[0];
    const float* amask         = (const float*)d_in[1];
    const unsigned char* qmask = (const unsigned char*)d_in[2];
    const float* Wq = (const float*)d_in[3];
    const float* bq = (const float*)d_in[4];
    const float* Wk = (const float*)d_in[5];
    const float* bk = (const float*)d_in[6];
    const float* Wv = (const float*)d_in[7];
    const float* bv = (const float*)d_in[8];
    float* out = (float*)d_out;

    split_hs_kernel<<<(SQ * EMB) / 256, 256>>>(hs);
    split_w_kernel<<<dim3(EMB / 32, EMB / 32, 3), dim3(32, 32)>>>(Wq, Wk, Wv);

    cudaFuncSetAttribute(qkv_mma_kernel,
                         cudaFuncAttributeMaxDynamicSharedMemorySize, QKV_SMEM);
    qkv_mma_kernel<<<dim3(EMB / 256, SQ / 128, 3), 256, QKV_SMEM>>>(bq, bk, bv);

    cudaFuncSetAttribute(attn_mma_kernel,
                         cudaFuncAttributeMaxDynamicSharedMemorySize, AT_SMEM);
    attn_mma_kernel<<<dim3(SQ / 128, NH), 128, AT_SMEM>>>(amask, qmask, out);
}

// round 11
// speedup vs baseline: 1.2955x; 1.2955x over previous
#include <cuda_runtime.h>
#include <cuda_bf16.h>
#include <math.h>
#include <stdint.h>

// Problem constants
#define SQ   4096
#define EMB  768
#define NH   12
#define HD   64
#define WIN  256
#define K2   2304   // 3 * 768 split-GEMM depth

// Scratch (allocation-free rule: __device__ globals)
__device__ float g_q[NH * SQ * HD];
__device__ float g_k[NH * SQ * HD];
__device__ float g_v[NH * SQ * HD];
__device__ __align__(16) __nv_bfloat16 g_as[(size_t)SQ * K2];        // A' [4096][2304] slabs [hi,hi,lo]
__device__ __align__(16) __nv_bfloat16 g_bs[(size_t)3 * EMB * K2];   // B'_z [768 n][2304 k] slabs [hi,lo,hi]

// ---------------------------------------------------------------------------
// PTX helpers — tcgen05 only under the sm_103a feature guard.
// ---------------------------------------------------------------------------
__device__ __forceinline__ uint32_t smem_u32(const void* p) {
    uint32_t a;
    asm("{ .reg .u64 t; cvta.to.shared.u64 t, %1; cvt.u32.u64 %0, t; }" : "=r"(a) : "l"(p));
    return a;
}
__device__ __forceinline__ uint32_t elect_one() {
    uint32_t pred;
    asm volatile("{\n\t.reg .pred p;\n\telect.sync _|p, 0xFFFFFFFF;\n\tselp.b32 %0, 1, 0, p;\n\t}" : "=r"(pred));
    return pred;
}
__device__ __forceinline__ void mbar_init(uint32_t mb, uint32_t cnt) {
    asm volatile("mbarrier.init.shared.b64 [%0], %1;" :: "r"(mb), "r"(cnt) : "memory");
}
__device__ __forceinline__ void mbar_wait(uint32_t mb, uint32_t phase) {
    asm volatile(
        "{\n\t.reg .pred P1;\n\t"
        "WL_%=:\n\t"
        "mbarrier.try_wait.parity.acquire.cta.shared::cta.b64 P1, [%0], %1, 0x989680;\n\t"
        "@P1 bra.uni WD_%=;\n\t"
        "bra.uni WL_%=;\n\t"
        "WD_%=:\n\t}"
        :: "r"(mb), "r"(phase) : "memory");
}

#if defined(__CUDA_ARCH_FEAT_SM103_ALL)
#define TC_OK 1
#else
#define TC_OK 0
#endif

#if TC_OK
__device__ __forceinline__ void mma_f16_ss(uint32_t d, uint64_t a, uint64_t b,
                                           uint32_t idesc, bool acc) {
    uint32_t en = acc ? 1u : 0u;
    asm volatile(
        "{\n\t.reg .pred p;\n\tsetp.ne.u32 p, %5, 0;\n\t"
        "tcgen05.mma.cta_group::1.kind::f16 [%0], %1, %2, %3, {%4, %4, %4, %4}, p;\n\t}"
        :: "r"(d), "l"(a), "l"(b), "r"(idesc), "r"(0u), "r"(en) : "memory");
}
__device__ __forceinline__ void tc_commit(uint32_t mb) {
    asm volatile("tcgen05.commit.cta_group::1.mbarrier::arrive::one.shared::cluster.b64 [%0];"
                 :: "r"(mb) : "memory");
}
#define TC_LD_X32(r, addr) \
    asm volatile( \
        "tcgen05.ld.sync.aligned.32x32b.x32.b32 " \
        "{%0, %1, %2, %3, %4, %5, %6, %7, " \
        " %8, %9, %10, %11, %12, %13, %14, %15, " \
        " %16, %17, %18, %19, %20, %21, %22, %23, " \
        " %24, %25, %26, %27, %28, %29, %30, %31}, [%32];" \
        : "=r"((r)[0]),  "=r"((r)[1]),  "=r"((r)[2]),  "=r"((r)[3]), \
          "=r"((r)[4]),  "=r"((r)[5]),  "=r"((r)[6]),  "=r"((r)[7]), \
          "=r"((r)[8]),  "=r"((r)[9]),  "=r"((r)[10]), "=r"((r)[11]), \
          "=r"((r)[12]), "=r"((r)[13]), "=r"((r)[14]), "=r"((r)[15]), \
          "=r"((r)[16]), "=r"((r)[17]), "=r"((r)[18]), "=r"((r)[19]), \
          "=r"((r)[20]), "=r"((r)[21]), "=r"((r)[22]), "=r"((r)[23]), \
          "=r"((r)[24]), "=r"((r)[25]), "=r"((r)[26]), "=r"((r)[27]), \
          "=r"((r)[28]), "=r"((r)[29]), "=r"((r)[30]), "=r"((r)[31]) \
        : "r"(addr))
#endif

static __device__ __forceinline__ uint64_t make_desc(uint32_t addr) {
    const uint64_t base = (2ull << 61) | (1ull << 46) | (64ull << 32) | (1ull << 16);
    return base | ((uint64_t)(addr >> 4) & 0x3FFF);
}
static __device__ __forceinline__ uint32_t sw128(uint32_t off) {
    return off ^ ((off >> 3) & 0x70);
}
static __device__ __forceinline__ uint32_t pack_bf2(float a, float b) {
    __nv_bfloat162 t = __floats2bfloat162_rn(a, b);
    return *(uint32_t*)&t;
}

// ---------------------------------------------------------------------------
// Split pre-pass: hs -> g_as (slabs hi,hi,lo)
// ---------------------------------------------------------------------------
__global__ void split_hs_kernel(const float* __restrict__ hs)
{
    int i = blockIdx.x * 256 + threadIdx.x;
    float x = hs[i];
    __nv_bfloat16 h = __float2bfloat16(x);
    __nv_bfloat16 l = __float2bfloat16(x - __bfloat162float(h));
    int row = i / EMB, k = i - row * EMB;
    __nv_bfloat16* p = &g_as[(size_t)row * K2];
    p[k] = h; p[EMB + k] = h; p[2 * EMB + k] = l;
}

__global__ void split_w_kernel(const float* __restrict__ Wq,
                               const float* __restrict__ Wk,
                               const float* __restrict__ Wv)
{
    __shared__ float t[32][33];
    const int z = blockIdx.z;
    const float* W = (z == 0) ? Wq : (z == 1) ? Wk : Wv;
    int k = blockIdx.y * 32 + threadIdx.y;
    int n = blockIdx.x * 32 + threadIdx.x;
    t[threadIdx.y][threadIdx.x] = W[(size_t)k * EMB + n];
    __syncthreads();
    int nn = blockIdx.x * 32 + threadIdx.y;
    int kk = blockIdx.y * 32 + threadIdx.x;
    float x = t[threadIdx.x][threadIdx.y];
    __nv_bfloat16 h = __float2bfloat16(x);
    __nv_bfloat16 l = __float2bfloat16(x - __bfloat162float(h));
    __nv_bfloat16* p = &g_bs[((size_t)z * EMB + nn) * K2];
    p[kk] = h; p[EMB + kk] = l; p[2 * EMB + kk] = h;
}

// ---------------------------------------------------------------------------
// QKV GEMM on tcgen05 (validated R6/R7, unchanged).
// ---------------------------------------------------------------------------
#define STAGE_BYTES 49152
#define QKV_SMEM (2 * STAGE_BYTES + 32)
#define QKV_IDESC 0x8400490u

__global__ __launch_bounds__(256) void qkv_mma_kernel(
    const float* __restrict__ bq, const float* __restrict__ bk,
    const float* __restrict__ bv)
{
    const int z = blockIdx.z;
    const float* bias = (z == 0) ? bq : (z == 1) ? bk : bv;
    float* dst = (z == 0) ? g_q : (z == 1) ? g_k : g_v;
    const int n0 = blockIdx.x * 256;
    const int m0 = blockIdx.y * 128;
    const int tid = threadIdx.x;

#if TC_OK
    extern __shared__ __align__(1024) char sm[];
    const uint32_t sb = smem_u32(sm);
    const int wid = tid >> 5, lid = tid & 31;

    const uint32_t ctrl = sb + 2 * STAGE_BYTES;
    const uint32_t mb[2] = { sb + 2 * STAGE_BYTES + 8, sb + 2 * STAGE_BYTES + 16 };

    if (tid == 0) { mbar_init(mb[0], 1); mbar_init(mb[1], 1); }
    if (wid == 0) {
        asm volatile("tcgen05.alloc.cta_group::1.sync.aligned.shared::cta.b32 [%0], %1;"
                     :: "r"(ctrl), "r"(256u) : "memory");
        asm volatile("tcgen05.relinquish_alloc_permit.cta_group::1.sync.aligned;");
    }
    __syncthreads();
    uint32_t tmem;
    asm volatile("ld.shared.b32 %0, [%1];" : "=r"(tmem) : "r"(ctrl));

    const __nv_bfloat16* Arow = &g_as[(size_t)m0 * K2];
    const __nv_bfloat16* Brow = &g_bs[((size_t)z * EMB + n0) * K2];

    int ph[2] = { 0, 0 };

    for (int c = 0; c < 36; c++) {
        const int s = c & 1;
        if (c >= 2) { mbar_wait(mb[s], ph[s]); ph[s] ^= 1; }
        const int kk = c * 64;
        char* stA = sm + s * STAGE_BYTES;
        char* stB = stA + 16384;

        #pragma unroll
        for (int j = 0; j < 4; j++) {
            int cid = tid + j * 256;
            int r = cid >> 3, c16 = cid & 7;
            uint32_t off = sw128((uint32_t)(r * 128 + c16 * 16));
            *(uint4*)(stA + off) = *(const uint4*)(Arow + (size_t)r * K2 + kk + c16 * 8);
        }
        #pragma unroll
        for (int j = 0; j < 8; j++) {
            int cid = tid + j * 256;
            int r = cid >> 3, c16 = cid & 7;
            uint32_t off = sw128((uint32_t)(r * 128 + c16 * 16));
            *(uint4*)(stB + off) = *(const uint4*)(Brow + (size_t)r * K2 + kk + c16 * 8);
        }
        asm volatile("fence.proxy.async.shared::cta;" ::: "memory");
        __syncthreads();

        if (wid == 0) {
            if (elect_one()) {
                uint64_t da = make_desc(sb + s * STAGE_BYTES);
                uint64_t db = make_desc(sb + s * STAGE_BYTES + 16384);
                #pragma unroll
                for (int k = 0; k < 4; k++)
                    mma_f16_ss(tmem, da + k * 2, db + k * 2, QKV_IDESC, (c > 0) || (k > 0));
                tc_commit(mb[s]);
            }
        }
    }

    mbar_wait(mb[1], ph[1]);
    asm volatile("tcgen05.fence::after_thread_sync;" ::: "memory");

    if (wid < 4) {
        const int r = wid * 32 + lid;
        const float scl = (z == 0) ? 0.125f : 1.0f;
        #pragma unroll
        for (int cb = 0; cb < 8; cb++) {
            uint32_t dr[32];
            TC_LD_X32(dr, tmem + cb * 32);
            asm volatile("tcgen05.wait::ld.sync.aligned;" ::: "memory");
            const int nbase = n0 + cb * 32;
            const int head = nbase >> 6;
            float* op = &dst[((size_t)head * SQ + m0 + r) * HD + (nbase & 63)];
            #pragma unroll
            for (int q = 0; q < 32; q += 4) {
                float4 v;
                v.x = (__uint_as_float(dr[q + 0]) + bias[nbase + q + 0]) * scl;
                v.y = (__uint_as_float(dr[q + 1]) + bias[nbase + q + 1]) * scl;
                v.z = (__uint_as_float(dr[q + 2]) + bias[nbase + q + 2]) * scl;
                v.w = (__uint_as_float(dr[q + 3]) + bias[nbase + q + 3]) * scl;
                *(float4*)&op[q] = v;
            }
        }
    }
    __syncthreads();
    if (wid == 0) {
        asm volatile("tcgen05.dealloc.cta_group::1.sync.aligned.b32 %0, %1;"
                     :: "r"(tmem), "r"(256u));
    }
#else
    const int r = tid >> 1;
    const int cb0 = (tid & 1) * 128;
    const float scl = (z == 0) ? 0.125f : 1.0f;
    const __nv_bfloat16* a = &g_as[(size_t)(m0 + r) * K2];
    for (int cc = 0; cc < 128; cc++) {
        const int n = n0 + cb0 + cc;
        const __nv_bfloat16* b = &g_bs[((size_t)z * EMB + n) * K2];
        float acc = 0.0f;
        for (int k = 0; k < K2; k++)
            acc += __bfloat162float(a[k]) * __bfloat162float(b[k]);
        const int head = n >> 6;
        dst[((size_t)head * SQ + m0 + r) * HD + (n & 63)] = (acc + bias[n]) * scl;
    }
#endif
}

// ---------------------------------------------------------------------------
// Banded attention on tcgen05. Per CTA = (head, 128 queries), block = 256.
// Single K/V buffer; vstg unioned with P (both gated by mbO); no-max softmax.
// Softmax split by column-half across two warpgroups. smem 97.3KB -> 2 CTA/SM.
// TMEM: S @0 (64), O @64 (64); alloc 128.
// ---------------------------------------------------------------------------
#define AT_QHI   0          // 16KB
#define AT_QLO   16384      // 16KB
#define AT_KHI   32768      // 8KB
#define AT_KLO   40960      // 8KB
#define AT_VTHI  49152      // 8KB
#define AT_VTLO  57344      // 8KB
#define AT_PHI   65536      // 16KB  (fp32 vstg [64][65] unioned here)
#define AT_PLO   81920      // 16KB
#define AT_KMSK  98304      // 64 floats
#define AT_LSUM  98560      // 2 x 128 floats
#define AT_CTRL  99584
#define AT_MBS   99592
#define AT_MBO   99600
#define AT_SMEM  99648
#define ATT_IDESC 0x8100490u   // f32 acc, bf16 a/b, N=64, M=128

__global__ __launch_bounds__(256, 2) void attn_mma_kernel(
    const float* __restrict__ amask,
    const unsigned char* __restrict__ qmask,
    float* __restrict__ out)
{
    const int h  = blockIdx.y;
    const int q0 = blockIdx.x * 128;
    const int tid = threadIdx.x;

#if TC_OK
    extern __shared__ __align__(1024) char sm[];
    const uint32_t sb = smem_u32(sm);
    const int wid = tid >> 5, lane = tid & 31;
    const int wg = wid >> 2;                    // warpgroup 0/1 -> col half
    const int wrow = (wid & 3) * 32 + lane;     // query row 0..127
    const int jc0 = wg * 32;                    // this WG's 32-col window
    const uint32_t mbS = sb + AT_MBS, mbO = sb + AT_MBO;
    float* kmsk = (float*)(sm + AT_KMSK);
    float* vstg = (float*)(sm + AT_PHI);        // fp32 [64][65], unioned with P
    float* lsum = (float*)(sm + AT_LSUM);

    if (tid == 0) { mbar_init(mbS, 1); mbar_init(mbO, 1); }
    if (wid == 0) {
        asm volatile("tcgen05.alloc.cta_group::1.sync.aligned.shared::cta.b32 [%0], %1;"
                     :: "r"(sb + AT_CTRL), "r"(128u) : "memory");
        asm volatile("tcgen05.relinquish_alloc_permit.cta_group::1.sync.aligned;");
    }
    __syncthreads();
    uint32_t tmem;
    asm volatile("ld.shared.b32 %0, [%1];" : "=r"(tmem) : "r"(sb + AT_CTRL));
    const uint32_t TM_S = tmem, TM_O = tmem + 64;

    const int gi = q0 + wrow;

    // ---- Prologue: Q tile -> Qhi/Qlo bf16 swizzled (2 threads per row) ----
    {
        const int r = tid >> 1, hf = (tid & 1) * 32;   // 32 floats per thread
        const float* qp = &g_q[((size_t)h * SQ + q0 + r) * HD + hf];
        float f[32];
        #pragma unroll
        for (int i = 0; i < 8; i++) *(float4*)&f[i * 4] = *(const float4*)&qp[i * 4];
        #pragma unroll
        for (int g = 0; g < 4; g++) {
            uint32_t off = sw128((uint32_t)(r * 128 + (hf + g * 8) * 2));
            uint4 hv, lv;
            #pragma unroll
            for (int e = 0; e < 8; e += 2) {
                float x0 = f[g * 8 + e], x1 = f[g * 8 + e + 1];
                float h0 = __bfloat162float(__float2bfloat16(x0));
                float h1 = __bfloat162float(__float2bfloat16(x1));
                ((uint32_t*)&hv)[e >> 1] = pack_bf2(h0, h1);
                ((uint32_t*)&lv)[e >> 1] = pack_bf2(x0 - h0, x1 - h1);
            }
            *(uint4*)(sm + AT_QHI + off) = hv;
            *(uint4*)(sm + AT_QLO + off) = lv;
        }
    }

    // valid band tiles
    int jbs[10]; int nt = 0;
    #pragma unroll
    for (int t = 0; t < 10; t++) {
        int jb = q0 - 256 + t * 64;
        if (jb >= 0 && jb < SQ) jbs[nt++] = jb;
    }

    const uint64_t dQh = make_desc(sb + AT_QHI), dQl = make_desc(sb + AT_QLO);
    const uint64_t dKh = make_desc(sb + AT_KHI), dKl = make_desc(sb + AT_KLO);
    const uint64_t dVh = make_desc(sb + AT_VTHI), dVl = make_desc(sb + AT_VTLO);
    const uint64_t dPh = make_desc(sb + AT_PHI), dPl = make_desc(sb + AT_PLO);

    float l_part = 0.0f;
    int phS = 0, phO = 0;

    for (int it = 0; it < nt; it++) {
        const int jb = jbs[it];

        // PV(it-1) must be complete before K/Vt/P(vstg) are overwritten
        if (it > 0) { mbar_wait(mbO, phO); phO ^= 1; }
        __syncthreads();   // all threads past the wait / prior-tile reads done

        // ---- stage: K -> Khi/Klo swizzled; V -> vstg; kmsk (4 thr/row) ----
        {
            const int rk = tid >> 2, qs = (tid & 3) * 16;   // 16 floats each
            const float* kp = &g_k[((size_t)h * SQ + jb + rk) * HD + qs];
            const float* vp = &g_v[((size_t)h * SQ + jb + rk) * HD + qs];
            float f[16];
            #pragma unroll
            for (int i = 0; i < 4; i++) *(float4*)&f[i * 4] = *(const float4*)&kp[i * 4];
            #pragma unroll
            for (int g = 0; g < 2; g++) {
                uint32_t off = sw128((uint32_t)(rk * 128 + (qs + g * 8) * 2));
                uint4 hv, lv;
                #pragma unroll
                for (int e = 0; e < 8; e += 2) {
                    float x0 = f[g * 8 + e], x1 = f[g * 8 + e + 1];
                    float h0 = __bfloat162float(__float2bfloat16(x0));
                    float h1 = __bfloat162float(__float2bfloat16(x1));
                    ((uint32_t*)&hv)[e >> 1] = pack_bf2(h0, h1);
                    ((uint32_t*)&lv)[e >> 1] = pack_bf2(x0 - h0, x1 - h1);
                }
                *(uint4*)(sm + AT_KHI + off) = hv;
                *(uint4*)(sm + AT_KLO + off) = lv;
            }
            #pragma unroll
            for (int i = 0; i < 16; i++) vstg[rk * 65 + qs + i] = vp[i];
            if (tid < 64)
                kmsk[tid] = (amask[jb + tid] != 0.0f) ? -1e8f : 0.0f;
        }
        __syncthreads();

        // ---- transpose vstg -> Vthi/Vtlo [dim][key] (4 thr/dim-row) ----
        {
            const int d = tid & 63, ks = (tid >> 6) * 16;
            float f[16];
            #pragma unroll
            for (int i = 0; i < 16; i++) f[i] = vstg[(ks + i) * 65 + d];
            #pragma unroll
            for (int g = 0; g < 2; g++) {
                uint32_t off = sw128((uint32_t)(d * 128 + (ks + g * 8) * 2));
                uint4 hv, lv;
                #pragma unroll
                for (int e = 0; e < 8; e += 2) {
                    float x0 = f[g * 8 + e], x1 = f[g * 8 + e + 1];
                    float h0 = __bfloat162float(__float2bfloat16(x0));
                    float h1 = __bfloat162float(__float2bfloat16(x1));
                    ((uint32_t*)&hv)[e >> 1] = pack_bf2(h0, h1);
                    ((uint32_t*)&lv)[e >> 1] = pack_bf2(x0 - h0, x1 - h1);
                }
                *(uint4*)(sm + AT_VTHI + off) = hv;
                *(uint4*)(sm + AT_VTLO + off) = lv;
            }
        }
        asm volatile("fence.proxy.async.shared::cta;" ::: "memory");
        __syncthreads();

        // ---- S = Q.K^T (3-term split) ----
        if (wid == 0 && elect_one()) {
            asm volatile("tcgen05.fence::after_thread_sync;" ::: "memory");
            #pragma unroll
            for (int k = 0; k < 4; k++) mma_f16_ss(TM_S, dQh + k * 2, dKh + k * 2, ATT_IDESC, k > 0);
            #pragma unroll
            for (int k = 0; k < 4; k++) mma_f16_ss(TM_S, dQh + k * 2, dKl + k * 2, ATT_IDESC, true);
            #pragma unroll
            for (int k = 0; k < 4; k++) mma_f16_ss(TM_S, dQl + k * 2, dKh + k * 2, ATT_IDESC, true);
            tc_commit(mbS);
        }
        mbar_wait(mbS, phS); phS ^= 1;
        asm volatile("tcgen05.fence::after_thread_sync;" ::: "memory");

        // ---- softmax: each WG handles its 32-col half of its row ----
        uint32_t s0[32];
        TC_LD_X32(s0, TM_S + jc0);
        asm volatile("tcgen05.wait::ld.sync.aligned;" ::: "memory");
        asm volatile("tcgen05.fence::before_thread_sync;" ::: "memory");

        float p[32];
        float rs = 0.0f;
        #pragma unroll
        for (int j = 0; j < 32; j++) {
            const int diff = gi - (jb + jc0 + j);
            const bool valid = (diff <= WIN) && (diff >= -WIN);
            float sv = __uint_as_float(s0[j]) + kmsk[jc0 + j];
            float pv = valid ? __expf(sv) : 0.0f;
            p[j] = pv;
            rs += pv;
        }
        l_part += rs;

        // ---- store P hi/lo (row wrow, cols jc0..jc0+31; overwrites vstg) ----
        #pragma unroll
        for (int g = 0; g < 4; g++) {
            uint32_t off = sw128((uint32_t)(wrow * 128 + (jc0 + g * 8) * 2));
            uint4 hv, lv;
            #pragma unroll
            for (int e = 0; e < 8; e += 2) {
                float x0 = p[g * 8 + e], x1 = p[g * 8 + e + 1];
                float h0 = __bfloat162float(__float2bfloat16(x0));
                float h1 = __bfloat162float(__float2bfloat16(x1));
                ((uint32_t*)&hv)[e >> 1] = pack_bf2(h0, h1);
                ((uint32_t*)&lv)[e >> 1] = pack_bf2(x0 - h0, x1 - h1);
            }
            *(uint4*)(sm + AT_PHI + off) = hv;
            *(uint4*)(sm + AT_PLO + off) = lv;
        }
        asm volatile("fence.proxy.async.shared::cta;" ::: "memory");
        __syncthreads();

        // ---- O += P.V (3-term split) ----
        if (wid == 0 && elect_one()) {
            asm volatile("tcgen05.fence::after_thread_sync;" ::: "memory");
            #pragma unroll
            for (int k = 0; k < 4; k++) mma_f16_ss(TM_O, dPh + k * 2, dVh + k * 2, ATT_IDESC, !(it == 0 && k == 0));
            #pragma unroll
            for (int k = 0; k < 4; k++) mma_f16_ss(TM_O, dPh + k * 2, dVl + k * 2, ATT_IDESC, true);
            #pragma unroll
            for (int k = 0; k < 4; k++) mma_f16_ss(TM_O, dPl + k * 2, dVh + k * 2, ATT_IDESC, true);
            tc_commit(mbO);
        }
    }

    // ---- Epilogue: reduce l across WG halves, normalize, write out ----
    lsum[wg * 128 + wrow] = l_part;
    mbar_wait(mbO, phO);
    asm volatile("tcgen05.fence::after_thread_sync;" ::: "memory");
    __syncthreads();
    {
        uint32_t o0[32];
        TC_LD_X32(o0, TM_O + jc0);
        asm volatile("tcgen05.wait::ld.sync.aligned;" ::: "memory");
        const float l_i = lsum[wrow] + lsum[128 + wrow];
        const float inv = (qmask[gi] != 0) ? 0.0f : 1.0f / l_i;
        float* op = &out[(size_t)gi * EMB + h * HD + jc0];
        #pragma unroll
        for (int j = 0; j < 32; j += 4) {
            float4 v;
            v.x = __uint_as_float(o0[j + 0]) * inv;
            v.y = __uint_as_float(o0[j + 1]) * inv;
            v.z = __uint_as_float(o0[j + 2]) * inv;
            v.w = __uint_as_float(o0[j + 3]) * inv;
            *(float4*)&op[j] = v;
        }
    }
    __syncthreads();
    if (wid == 0) {
        asm volatile("tcgen05.dealloc.cta_group::1.sync.aligned.b32 %0, %1;"
                     :: "r"(tmem), "r"(128u));
    }
#else
    // Generic fallback (compute_103 PTX pass only; never runs on GB300).
    if (tid < 128) {
        const int gi = q0 + tid;
        const float* qp = &g_q[((size_t)h * SQ + gi) * HD];
        float l = 0.0f, O[64];
        #pragma unroll
        for (int d = 0; d < 64; d++) O[d] = 0.0f;
        int lo = gi - WIN; if (lo < 0) lo = 0;
        int hi = gi + WIN; if (hi > SQ - 1) hi = SQ - 1;
        for (int gj = lo; gj <= hi; gj++) {
            const float* kp = &g_k[((size_t)h * SQ + gj) * HD];
            float s = 0.0f;
            for (int d = 0; d < 64; d++) s += qp[d] * kp[d];
            s += (amask[gj] != 0.0f) ? -1e8f : 0.0f;
            float pv = __expf(s);
            l += pv;
            const float* vp = &g_v[((size_t)h * SQ + gj) * HD];
            for (int d = 0; d < 64; d++) O[d] += pv * vp[d];
        }
        const float inv = (qmask[gi] != 0) ? 0.0f : 1.0f / l;
        float* op = &out[(size_t)gi * EMB + h * HD];
        for (int d = 0; d < 64; d++) op[d] = O[d] * inv;
    }
#endif
}

// ---------------------------------------------------------------------------
// Launch
// ---------------------------------------------------------------------------
extern "C" void kernel_launch(void* const* d_in, const int* in_sizes, int n_in,
                              void* d_out, int out_size)
{
    const float* hs            = (const float*)d_in[0];
    const float* amask         = (const float*)d_in[1];
    const unsigned char* qmask = (const unsigned char*)d_in[2];
    const float* Wq = (const float*)d_in[3];
    const float* bq = (const float*)d_in[4];
    const float* Wk = (const float*)d_in[5];
    const float* bk = (const float*)d_in[6];
    const float* Wv = (const float*)d_in[7];
    const float* bv = (const float*)d_in[8];
    float* out = (float*)d_out;

    split_hs_kernel<<<(SQ * EMB) / 256, 256>>>(hs);
    split_w_kernel<<<dim3(EMB / 32, EMB / 32, 3), dim3(32, 32)>>>(Wq, Wk, Wv);

    cudaFuncSetAttribute(qkv_mma_kernel,
                         cudaFuncAttributeMaxDynamicSharedMemorySize, QKV_SMEM);
    qkv_mma_kernel<<<dim3(EMB / 256, SQ / 128, 3), 256, QKV_SMEM>>>(bq, bk, bv);

    cudaFuncSetAttribute(attn_mma_kernel,
                         cudaFuncAttributeMaxDynamicSharedMemorySize, AT_SMEM);
    attn_mma_kernel<<<dim3(SQ / 128, NH), 256, AT_SMEM>>>(amask, qmask, out);
}

// round 13
// speedup vs baseline: 1.6373x; 1.2638x over previous
#include <cuda_runtime.h>
#include <cuda_bf16.h>
#include <math.h>
#include <stdint.h>

// Problem constants
#define SQ   4096
#define EMB  768
#define NH   12
#define HD   64
#define WIN  256
#define K2   2304   // 3 * 768 split-GEMM depth

// Scratch (allocation-free rule: __device__ globals)
// g_v layout is TRANSPOSED per head: [NH][HD][SQ]
__device__ float g_q[NH * SQ * HD];
__device__ float g_k[NH * SQ * HD];
__device__ float g_v[NH * HD * SQ];
__device__ __align__(16) __nv_bfloat16 g_as[(size_t)SQ * K2];        // A' [4096][2304] slabs [hi,hi,lo]
__device__ __align__(16) __nv_bfloat16 g_bs[(size_t)3 * EMB * K2];   // B'_z [768 n][2304 k] slabs [hi,lo,hi]

// ---------------------------------------------------------------------------
// PTX helpers — tcgen05 only under the sm_103a feature guard.
// ---------------------------------------------------------------------------
__device__ __forceinline__ uint32_t smem_u32(const void* p) {
    uint32_t a;
    asm("{ .reg .u64 t; cvta.to.shared.u64 t, %1; cvt.u32.u64 %0, t; }" : "=r"(a) : "l"(p));
    return a;
}
__device__ __forceinline__ uint32_t elect_one() {
    uint32_t pred;
    asm volatile("{\n\t.reg .pred p;\n\telect.sync _|p, 0xFFFFFFFF;\n\tselp.b32 %0, 1, 0, p;\n\t}" : "=r"(pred));
    return pred;
}
__device__ __forceinline__ void mbar_init(uint32_t mb, uint32_t cnt) {
    asm volatile("mbarrier.init.shared.b64 [%0], %1;" :: "r"(mb), "r"(cnt) : "memory");
}
__device__ __forceinline__ void mbar_wait(uint32_t mb, uint32_t phase) {
    asm volatile(
        "{\n\t.reg .pred P1;\n\t"
        "WL_%=:\n\t"
        "mbarrier.try_wait.parity.acquire.cta.shared::cta.b64 P1, [%0], %1, 0x989680;\n\t"
        "@P1 bra.uni WD_%=;\n\t"
        "bra.uni WL_%=;\n\t"
        "WD_%=:\n\t}"
        :: "r"(mb), "r"(phase) : "memory");
}

#if defined(__CUDA_ARCH_FEAT_SM103_ALL)
#define TC_OK 1
#else
#define TC_OK 0
#endif

#if TC_OK
__device__ __forceinline__ void mma_f16_ss(uint32_t d, uint64_t a, uint64_t b,
                                           uint32_t idesc, bool acc) {
    uint32_t en = acc ? 1u : 0u;
    asm volatile(
        "{\n\t.reg .pred p;\n\tsetp.ne.u32 p, %5, 0;\n\t"
        "tcgen05.mma.cta_group::1.kind::f16 [%0], %1, %2, %3, {%4, %4, %4, %4}, p;\n\t}"
        :: "r"(d), "l"(a), "l"(b), "r"(idesc), "r"(0u), "r"(en) : "memory");
}
__device__ __forceinline__ void tc_commit(uint32_t mb) {
    asm volatile("tcgen05.commit.cta_group::1.mbarrier::arrive::one.shared::cluster.b64 [%0];"
                 :: "r"(mb) : "memory");
}
#define TC_LD_X32(r, addr) \
    asm volatile( \
        "tcgen05.ld.sync.aligned.32x32b.x32.b32 " \
        "{%0, %1, %2, %3, %4, %5, %6, %7, " \
        " %8, %9, %10, %11, %12, %13, %14, %15, " \
        " %16, %17, %18, %19, %20, %21, %22, %23, " \
        " %24, %25, %26, %27, %28, %29, %30, %31}, [%32];" \
        : "=r"((r)[0]),  "=r"((r)[1]),  "=r"((r)[2]),  "=r"((r)[3]), \
          "=r"((r)[4]),  "=r"((r)[5]),  "=r"((r)[6]),  "=r"((r)[7]), \
          "=r"((r)[8]),  "=r"((r)[9]),  "=r"((r)[10]), "=r"((r)[11]), \
          "=r"((r)[12]), "=r"((r)[13]), "=r"((r)[14]), "=r"((r)[15]), \
          "=r"((r)[16]), "=r"((r)[17]), "=r"((r)[18]), "=r"((r)[19]), \
          "=r"((r)[20]), "=r"((r)[21]), "=r"((r)[22]), "=r"((r)[23]), \
          "=r"((r)[24]), "=r"((r)[25]), "=r"((r)[26]), "=r"((r)[27]), \
          "=r"((r)[28]), "=r"((r)[29]), "=r"((r)[30]), "=r"((r)[31]) \
        : "r"(addr))
#endif

static __device__ __forceinline__ uint64_t make_desc(uint32_t addr) {
    const uint64_t base = (2ull << 61) | (1ull << 46) | (64ull << 32) | (1ull << 16);
    return base | ((uint64_t)(addr >> 4) & 0x3FFF);
}
static __device__ __forceinline__ uint32_t sw128(uint32_t off) {
    return off ^ ((off >> 3) & 0x70);
}
static __device__ __forceinline__ uint32_t pack_bf2(float a, float b) {
    __nv_bfloat162 t = __floats2bfloat162_rn(a, b);
    return *(uint32_t*)&t;
}

// ---------------------------------------------------------------------------
// Split pre-pass: hs -> g_as (slabs hi,hi,lo)
// ---------------------------------------------------------------------------
__global__ void split_hs_kernel(const float* __restrict__ hs)
{
    int i = blockIdx.x * 256 + threadIdx.x;
    float x = hs[i];
    __nv_bfloat16 h = __float2bfloat16(x);
    __nv_bfloat16 l = __float2bfloat16(x - __bfloat162float(h));
    int row = i / EMB, k = i - row * EMB;
    __nv_bfloat16* p = &g_as[(size_t)row * K2];
    p[k] = h; p[EMB + k] = h; p[2 * EMB + k] = l;
}

__global__ void split_w_kernel(const float* __restrict__ Wq,
                               const float* __restrict__ Wk,
                               const float* __restrict__ Wv)
{
    __shared__ float t[32][33];
    const int z = blockIdx.z;
    const float* W = (z == 0) ? Wq : (z == 1) ? Wk : Wv;
    int k = blockIdx.y * 32 + threadIdx.y;
    int n = blockIdx.x * 32 + threadIdx.x;
    t[threadIdx.y][threadIdx.x] = W[(size_t)k * EMB + n];
    __syncthreads();
    int nn = blockIdx.x * 32 + threadIdx.y;
    int kk = blockIdx.y * 32 + threadIdx.x;
    float x = t[threadIdx.x][threadIdx.y];
    __nv_bfloat16 h = __float2bfloat16(x);
    __nv_bfloat16 l = __float2bfloat16(x - __bfloat162float(h));
    __nv_bfloat16* p = &g_bs[((size_t)z * EMB + nn) * K2];
    p[kk] = h; p[EMB + kk] = l; p[2 * EMB + kk] = h;
}

// ---------------------------------------------------------------------------
// QKV GEMM on tcgen05 (validated). z==2 (V) writes TRANSPOSED [NH][HD][SQ].
// ---------------------------------------------------------------------------
#define STAGE_BYTES 49152
#define QKV_SMEM (2 * STAGE_BYTES + 32)
#define QKV_IDESC 0x8400490u

__global__ __launch_bounds__(256) void qkv_mma_kernel(
    const float* __restrict__ bq, const float* __restrict__ bk,
    const float* __restrict__ bv)
{
    const int z = blockIdx.z;
    const float* bias = (z == 0) ? bq : (z == 1) ? bk : bv;
    float* dst = (z == 0) ? g_q : (z == 1) ? g_k : g_v;
    const int n0 = blockIdx.x * 256;
    const int m0 = blockIdx.y * 128;
    const int tid = threadIdx.x;

#if TC_OK
    extern __shared__ __align__(1024) char sm[];
    const uint32_t sb = smem_u32(sm);
    const int wid = tid >> 5, lid = tid & 31;

    const uint32_t ctrl = sb + 2 * STAGE_BYTES;
    const uint32_t mb[2] = { sb + 2 * STAGE_BYTES + 8, sb + 2 * STAGE_BYTES + 16 };

    if (tid == 0) { mbar_init(mb[0], 1); mbar_init(mb[1], 1); }
    if (wid == 0) {
        asm volatile("tcgen05.alloc.cta_group::1.sync.aligned.shared::cta.b32 [%0], %1;"
                     :: "r"(ctrl), "r"(256u) : "memory");
        asm volatile("tcgen05.relinquish_alloc_permit.cta_group::1.sync.aligned;");
    }
    __syncthreads();
    uint32_t tmem;
    asm volatile("ld.shared.b32 %0, [%1];" : "=r"(tmem) : "r"(ctrl));

    const __nv_bfloat16* Arow = &g_as[(size_t)m0 * K2];
    const __nv_bfloat16* Brow = &g_bs[((size_t)z * EMB + n0) * K2];

    int ph[2] = { 0, 0 };

    for (int c = 0; c < 36; c++) {
        const int s = c & 1;
        if (c >= 2) { mbar_wait(mb[s], ph[s]); ph[s] ^= 1; }
        const int kk = c * 64;
        char* stA = sm + s * STAGE_BYTES;
        char* stB = stA + 16384;

        #pragma unroll
        for (int j = 0; j < 4; j++) {
            int cid = tid + j * 256;
            int r = cid >> 3, c16 = cid & 7;
            uint32_t off = sw128((uint32_t)(r * 128 + c16 * 16));
            *(uint4*)(stA + off) = *(const uint4*)(Arow + (size_t)r * K2 + kk + c16 * 8);
        }
        #pragma unroll
        for (int j = 0; j < 8; j++) {
            int cid = tid + j * 256;
            int r = cid >> 3, c16 = cid & 7;
            uint32_t off = sw128((uint32_t)(r * 128 + c16 * 16));
            *(uint4*)(stB + off) = *(const uint4*)(Brow + (size_t)r * K2 + kk + c16 * 8);
        }
        asm volatile("fence.proxy.async.shared::cta;" ::: "memory");
        __syncthreads();

        if (wid == 0) {
            if (elect_one()) {
                uint64_t da = make_desc(sb + s * STAGE_BYTES);
                uint64_t db = make_desc(sb + s * STAGE_BYTES + 16384);
                #pragma unroll
                for (int k = 0; k < 4; k++)
                    mma_f16_ss(tmem, da + k * 2, db + k * 2, QKV_IDESC, (c > 0) || (k > 0));
                tc_commit(mb[s]);
            }
        }
    }

    mbar_wait(mb[1], ph[1]);
    asm volatile("tcgen05.fence::after_thread_sync;" ::: "memory");

    if (wid < 4) {
        const int r = wid * 32 + lid;
        const float scl = (z == 0) ? 0.125f : 1.0f;
        #pragma unroll
        for (int cb = 0; cb < 8; cb++) {
            uint32_t dr[32];
            TC_LD_X32(dr, tmem + cb * 32);
            asm volatile("tcgen05.wait::ld.sync.aligned;" ::: "memory");
            const int nbase = n0 + cb * 32;
            const int head = nbase >> 6;
            if (z == 2) {
                // transposed: dst[head][d][s], lanes write consecutive s
                #pragma unroll
                for (int q = 0; q < 32; q++) {
                    float v = __uint_as_float(dr[q]) + bias[nbase + q];
                    dst[((size_t)head * HD + (nbase & 63) + q) * SQ + m0 + r] = v;
                }
            } else {
                float* op = &dst[((size_t)head * SQ + m0 + r) * HD + (nbase & 63)];
                #pragma unroll
                for (int q = 0; q < 32; q += 4) {
                    float4 v;
                    v.x = (__uint_as_float(dr[q + 0]) + bias[nbase + q + 0]) * scl;
                    v.y = (__uint_as_float(dr[q + 1]) + bias[nbase + q + 1]) * scl;
                    v.z = (__uint_as_float(dr[q + 2]) + bias[nbase + q + 2]) * scl;
                    v.w = (__uint_as_float(dr[q + 3]) + bias[nbase + q + 3]) * scl;
                    *(float4*)&op[q] = v;
                }
            }
        }
    }
    __syncthreads();
    if (wid == 0) {
        asm volatile("tcgen05.dealloc.cta_group::1.sync.aligned.b32 %0, %1;"
                     :: "r"(tmem), "r"(256u));
    }
#else
    const int r = tid >> 1;
    const int cb0 = (tid & 1) * 128;
    const float scl = (z == 0) ? 0.125f : 1.0f;
    const __nv_bfloat16* a = &g_as[(size_t)(m0 + r) * K2];
    for (int cc = 0; cc < 128; cc++) {
        const int n = n0 + cb0 + cc;
        const __nv_bfloat16* b = &g_bs[((size_t)z * EMB + n) * K2];
        float acc = 0.0f;
        for (int k = 0; k < K2; k++)
            acc += __bfloat162float(a[k]) * __bfloat162float(b[k]);
        const int head = n >> 6;
        float v = (acc + bias[n]) * scl;
        if (z == 2)
            dst[((size_t)head * HD + (n & 63)) * SQ + m0 + r] = v;
        else
            dst[((size_t)head * SQ + m0 + r) * HD + (n & 63)] = v;
    }
#endif
}

// ---------------------------------------------------------------------------
// Banded attention on tcgen05. Per CTA = (head, 128 queries), block = 256.
// V pre-transposed in global -> no in-kernel transpose. Recycled-K pipelining:
// stage K(t+1)+issue S(t+1) right after LDTM S(t), overlapping softmax/PV(t).
// smem 97.6KB -> 2 CTA/SM. TMEM: S @0 (64), O @64 (64); alloc 128.
// ---------------------------------------------------------------------------
#define AT_QHI   0          // 16KB
#define AT_QLO   16384      // 16KB
#define AT_KHI   32768      // 8KB
#define AT_KLO   40960      // 8KB
#define AT_VTHI  49152      // 8KB
#define AT_VTLO  57344      // 8KB
#define AT_PHI   65536      // 16KB
#define AT_PLO   81920      // 16KB
#define AT_KMSK  98304      // 2 x 64 floats
#define AT_LSUM  98816      // 2 x 128 floats
#define AT_CTRL  99840
#define AT_MBS   99848
#define AT_MBO   99856
#define AT_SMEM  99904
#define ATT_IDESC 0x8100490u   // f32 acc, bf16 a/b, N=64, M=128

__global__ __launch_bounds__(256, 2) void attn_mma_kernel(
    const float* __restrict__ amask,
    const unsigned char* __restrict__ qmask,
    float* __restrict__ out)
{
    const int h  = blockIdx.y;
    const int q0 = blockIdx.x * 128;
    const int tid = threadIdx.x;

#if TC_OK
    extern __shared__ __align__(1024) char sm[];
    const uint32_t sb = smem_u32(sm);
    const int wid = tid >> 5, lane = tid & 31;
    const int wg = wid >> 2;                    // warpgroup 0/1 -> col half
    const int wrow = (wid & 3) * 32 + lane;     // query row 0..127
    const int jc0 = wg * 32;                    // this WG's 32-col window
    const uint32_t mbS = sb + AT_MBS, mbO = sb + AT_MBO;
    float* kmsk = (float*)(sm + AT_KMSK);
    float* lsum = (float*)(sm + AT_LSUM);

    if (tid == 0) { mbar_init(mbS, 1); mbar_init(mbO, 1); }
    if (wid == 0) {
        asm volatile("tcgen05.alloc.cta_group::1.sync.aligned.shared::cta.b32 [%0], %1;"
                     :: "r"(sb + AT_CTRL), "r"(128u) : "memory");
        asm volatile("tcgen05.relinquish_alloc_permit.cta_group::1.sync.aligned;");
    }
    __syncthreads();
    uint32_t tmem;
    asm volatile("ld.shared.b32 %0, [%1];" : "=r"(tmem) : "r"(sb + AT_CTRL));
    const uint32_t TM_S = tmem, TM_O = tmem + 64;

    const int gi = q0 + wrow;

    // ---- Prologue: Q tile -> Qhi/Qlo bf16 swizzled (2 threads per row) ----
    {
        const int r = tid >> 1, hf = (tid & 1) * 32;
        const float* qp = &g_q[((size_t)h * SQ + q0 + r) * HD + hf];
        float f[32];
        #pragma unroll
        for (int i = 0; i < 8; i++) *(float4*)&f[i * 4] = *(const float4*)&qp[i * 4];
        #pragma unroll
        for (int g = 0; g < 4; g++) {
            uint32_t off = sw128((uint32_t)(r * 128 + (hf + g * 8) * 2));
            uint4 hv, lv;
            #pragma unroll
            for (int e = 0; e < 8; e += 2) {
                float x0 = f[g * 8 + e], x1 = f[g * 8 + e + 1];
                float h0 = __bfloat162float(__float2bfloat16(x0));
                float h1 = __bfloat162float(__float2bfloat16(x1));
                ((uint32_t*)&hv)[e >> 1] = pack_bf2(h0, h1);
                ((uint32_t*)&lv)[e >> 1] = pack_bf2(x0 - h0, x1 - h1);
            }
            *(uint4*)(sm + AT_QHI + off) = hv;
            *(uint4*)(sm + AT_QLO + off) = lv;
        }
    }

    // valid band tiles
    int jbs[10]; int nt = 0;
    #pragma unroll
    for (int t = 0; t < 10; t++) {
        int jb = q0 - 256 + t * 64;
        if (jb >= 0 && jb < SQ) jbs[nt++] = jb;
    }

    const uint64_t dQh = make_desc(sb + AT_QHI), dQl = make_desc(sb + AT_QLO);
    const uint64_t dKh = make_desc(sb + AT_KHI), dKl = make_desc(sb + AT_KLO);
    const uint64_t dVh = make_desc(sb + AT_VTHI), dVl = make_desc(sb + AT_VTLO);
    const uint64_t dPh = make_desc(sb + AT_PHI), dPl = make_desc(sb + AT_PLO);

    // stage K(jb) + kmsk into buffer kb (4 threads per key row)
    auto stage_k = [&](int jb, int kb) {
        const int rk = tid >> 2, qs = (tid & 3) * 16;
        const float* kp = &g_k[((size_t)h * SQ + jb + rk) * HD + qs];
        float f[16];
        #pragma unroll
        for (int i = 0; i < 4; i++) *(float4*)&f[i * 4] = *(const float4*)&kp[i * 4];
        #pragma unroll
        for (int g = 0; g < 2; g++) {
            uint32_t off = sw128((uint32_t)(rk * 128 + (qs + g * 8) * 2));
            uint4 hv, lv;
            #pragma unroll
            for (int e = 0; e < 8; e += 2) {
                float x0 = f[g * 8 + e], x1 = f[g * 8 + e + 1];
                float h0 = __bfloat162float(__float2bfloat16(x0));
                float h1 = __bfloat162float(__float2bfloat16(x1));
                ((uint32_t*)&hv)[e >> 1] = pack_bf2(h0, h1);
                ((uint32_t*)&lv)[e >> 1] = pack_bf2(x0 - h0, x1 - h1);
            }
            *(uint4*)(sm + AT_KHI + off) = hv;
            *(uint4*)(sm + AT_KLO + off) = lv;
        }
        if (tid < 64)
            kmsk[kb * 64 + tid] = (amask[jb + tid] != 0.0f) ? -1e8f : 0.0f;
    };

    auto issue_S = [&]() {
        asm volatile("tcgen05.fence::after_thread_sync;" ::: "memory");
        #pragma unroll
        for (int k = 0; k < 4; k++) mma_f16_ss(TM_S, dQh + k * 2, dKh + k * 2, ATT_IDESC, k > 0);
        #pragma unroll
        for (int k = 0; k < 4; k++) mma_f16_ss(TM_S, dQh + k * 2, dKl + k * 2, ATT_IDESC, true);
        #pragma unroll
        for (int k = 0; k < 4; k++) mma_f16_ss(TM_S, dQl + k * 2, dKh + k * 2, ATT_IDESC, true);
        tc_commit(mbS);
    };

    float l_part = 0.0f;
    int phS = 0, phO = 0;

    // ---- Prologue: stage K(0), issue S(0) ----
    stage_k(jbs[0], 0);
    asm volatile("fence.proxy.async.shared::cta;" ::: "memory");
    __syncthreads();
    if (wid == 0 && elect_one()) issue_S();

    for (int it = 0; it < nt; it++) {
        const int b = it & 1;
        const bool more = (it + 1 < nt);
        const int jb = jbs[it];

        // ---- wait S(t), read scores ----
        mbar_wait(mbS, phS); phS ^= 1;
        asm volatile("tcgen05.fence::after_thread_sync;" ::: "memory");
        uint32_t s0[32];
        TC_LD_X32(s0, TM_S + jc0);
        asm volatile("tcgen05.wait::ld.sync.aligned;" ::: "memory");
        asm volatile("tcgen05.fence::before_thread_sync;" ::: "memory");

        // ---- K smem is free: stage K(t+1), issue S(t+1) (overlaps softmax) --
        if (more) stage_k(jbs[it + 1], b ^ 1);
        asm volatile("fence.proxy.async.shared::cta;" ::: "memory");
        __syncthreads();
        if (more && wid == 0 && elect_one()) issue_S();

        // ---- softmax on this WG's 32-col half ----
        float p[32];
        float rs = 0.0f;
        #pragma unroll
        for (int j = 0; j < 32; j++) {
            const int diff = gi - (jb + jc0 + j);
            const bool valid = (diff <= WIN) && (diff >= -WIN);
            float sv = __uint_as_float(s0[j]) + kmsk[b * 64 + jc0 + j];
            float pv = valid ? __expf(sv) : 0.0f;
            p[j] = pv;
            rs += pv;
        }
        l_part += rs;

        // ---- prefetch Vt(t) rows from global (pre-transposed) ----
        const int vd = tid >> 2, vks = (tid & 3) * 16;
        float vf[16];
        {
            const float* vp = &g_v[((size_t)h * HD + vd) * SQ + jb + vks];
            #pragma unroll
            for (int i = 0; i < 4; i++) *(float4*)&vf[i * 4] = *(const float4*)&vp[i * 4];
        }

        // PV(t-1) must be complete before Vt/P overwrite
        if (it > 0) { mbar_wait(mbO, phO); phO ^= 1; }

        // ---- store Vt hi/lo ----
        #pragma unroll
        for (int g = 0; g < 2; g++) {
            uint32_t off = sw128((uint32_t)(vd * 128 + (vks + g * 8) * 2));
            uint4 hv, lv;
            #pragma unroll
            for (int e = 0; e < 8; e += 2) {
                float x0 = vf[g * 8 + e], x1 = vf[g * 8 + e + 1];
                float h0 = __bfloat162float(__float2bfloat16(x0));
                float h1 = __bfloat162float(__float2bfloat16(x1));
                ((uint32_t*)&hv)[e >> 1] = pack_bf2(h0, h1);
                ((uint32_t*)&lv)[e >> 1] = pack_bf2(x0 - h0, x1 - h1);
            }
            *(uint4*)(sm + AT_VTHI + off) = hv;
            *(uint4*)(sm + AT_VTLO + off) = lv;
        }

        // ---- store P hi/lo (row wrow, cols jc0..jc0+31) ----
        #pragma unroll
        for (int g = 0; g < 4; g++) {
            uint32_t off = sw128((uint32_t)(wrow * 128 + (jc0 + g * 8) * 2));
            uint4 hv, lv;
            #pragma unroll
            for (int e = 0; e < 8; e += 2) {
                float x0 = p[g * 8 + e], x1 = p[g * 8 + e + 1];
                float h0 = __bfloat162float(__float2bfloat16(x0));
                float h1 = __bfloat162float(__float2bfloat16(x1));
                ((uint32_t*)&hv)[e >> 1] = pack_bf2(h0, h1);
                ((uint32_t*)&lv)[e >> 1] = pack_bf2(x0 - h0, x1 - h1);
            }
            *(uint4*)(sm + AT_PHI + off) = hv;
            *(uint4*)(sm + AT_PLO + off) = lv;
        }
        asm volatile("fence.proxy.async.shared::cta;" ::: "memory");
        __syncthreads();

        // ---- O += P.V (3-term split) ----
        if (wid == 0 && elect_one()) {
            asm volatile("tcgen05.fence::after_thread_sync;" ::: "memory");
            #pragma unroll
            for (int k = 0; k < 4; k++) mma_f16_ss(TM_O, dPh + k * 2, dVh + k * 2, ATT_IDESC, !(it == 0 && k == 0));
            #pragma unroll
            for (int k = 0; k < 4; k++) mma_f16_ss(TM_O, dPh + k * 2, dVl + k * 2, ATT_IDESC, true);
            #pragma unroll
            for (int k = 0; k < 4; k++) mma_f16_ss(TM_O, dPl + k * 2, dVh + k * 2, ATT_IDESC, true);
            tc_commit(mbO);
        }
    }

    // ---- Epilogue: reduce l across WG halves, normalize, write out ----
    lsum[wg * 128 + wrow] = l_part;
    mbar_wait(mbO, phO);
    asm volatile("tcgen05.fence::after_thread_sync;" ::: "memory");
    __syncthreads();
    {
        uint32_t o0[32];
        TC_LD_X32(o0, TM_O + jc0);
        asm volatile("tcgen05.wait::ld.sync.aligned;" ::: "memory");
        const float l_i = lsum[wrow] + lsum[128 + wrow];
        const float inv = (qmask[gi] != 0) ? 0.0f : 1.0f / l_i;
        float* op = &out[(size_t)gi * EMB + h * HD + jc0];
        #pragma unroll
        for (int j = 0; j < 32; j += 4) {
            float4 v;
            v.x = __uint_as_float(o0[j + 0]) * inv;
            v.y = __uint_as_float(o0[j + 1]) * inv;
            v.z = __uint_as_float(o0[j + 2]) * inv;
            v.w = __uint_as_float(o0[j + 3]) * inv;
            *(float4*)&op[j] = v;
        }
    }
    __syncthreads();
    if (wid == 0) {
        asm volatile("tcgen05.dealloc.cta_group::1.sync.aligned.b32 %0, %1;"
                     :: "r"(tmem), "r"(128u));
    }
#else
    // Generic fallback (compute_103 PTX pass only; never runs on GB300).
    if (tid < 128) {
        const int gi = q0 + tid;
        const float* qp = &g_q[((size_t)h * SQ + gi) * HD];
        float l = 0.0f, O[64];
        #pragma unroll
        for (int d = 0; d < 64; d++) O[d] = 0.0f;
        int lo = gi - WIN; if (lo < 0) lo = 0;
        int hi = gi + WIN; if (hi > SQ - 1) hi = SQ - 1;
        for (int gj = lo; gj <= hi; gj++) {
            const float* kp = &g_k[((size_t)h * SQ + gj) * HD];
            float s = 0.0f;
            for (int d = 0; d < 64; d++) s += qp[d] * kp[d];
            s += (amask[gj] != 0.0f) ? -1e8f : 0.0f;
            float pv = __expf(s);
            l += pv;
            for (int d = 0; d < 64; d++)
                O[d] += pv * g_v[((size_t)h * HD + d) * SQ + gj];
        }
        const float inv = (qmask[gi] != 0) ? 0.0f : 1.0f / l;
        float* op = &out[(size_t)gi * EMB + h * HD];
        for (int d = 0; d < 64; d++) op[d] = O[d] * inv;
    }
#endif
}

// ---------------------------------------------------------------------------
// Launch
// ---------------------------------------------------------------------------
extern "C" void kernel_launch(void* const* d_in, const int* in_sizes, int n_in,
                              void* d_out, int out_size)
{
    const float* hs            = (const float*)d_in[0];
    const float* amask         = (const float*)d_in[1];
    const unsigned char* qmask = (const unsigned char*)d_in[2];
    const float* Wq = (const float*)d_in[3];
    const float* bq = (const float*)d_in[4];
    const float* Wk = (const float*)d_in[5];
    const float* bk = (const float*)d_in[6];
    const float* Wv = (const float*)d_in[7];
    const float* bv = (const float*)d_in[8];
    float* out = (float*)d_out;

    split_hs_kernel<<<(SQ * EMB) / 256, 256>>>(hs);
    split_w_kernel<<<dim3(EMB / 32, EMB / 32, 3), dim3(32, 32)>>>(Wq, Wk, Wv);

    cudaFuncSetAttribute(qkv_mma_kernel,
                         cudaFuncAttributeMaxDynamicSharedMemorySize, QKV_SMEM);
    qkv_mma_kernel<<<dim3(EMB / 256, SQ / 128, 3), 256, QKV_SMEM>>>(bq, bk, bv);

    cudaFuncSetAttribute(attn_mma_kernel,
                         cudaFuncAttributeMaxDynamicSharedMemorySize, AT_SMEM);
    attn_mma_kernel<<<dim3(SQ / 128, NH), 256, AT_SMEM>>>(amask, qmask, out);
}

// round 14
// speedup vs baseline: 1.6763x; 1.0238x over previous
#include <cuda_runtime.h>
#include <cuda_bf16.h>
#include <math.h>
#include <stdint.h>

// Problem constants
#define SQ   4096
#define EMB  768
#define NH   12
#define HD   64
#define WIN  256
#define K2   2304   // 3 * 768 split-GEMM depth

// Scratch (allocation-free rule: __device__ globals)
// K stored pre-split: g_khi/g_klo [NH][SQ][HD] bf16
// V stored pre-split AND pre-transposed: g_vthi/g_vtlo [NH][HD][SQ] bf16
__device__ float g_q[NH * SQ * HD];
__device__ __align__(16) __nv_bfloat16 g_khi[NH * SQ * HD];
__device__ __align__(16) __nv_bfloat16 g_klo[NH * SQ * HD];
__device__ __align__(16) __nv_bfloat16 g_vthi[NH * HD * SQ];
__device__ __align__(16) __nv_bfloat16 g_vtlo[NH * HD * SQ];
__device__ __align__(16) __nv_bfloat16 g_as[(size_t)SQ * K2];        // A' [4096][2304] slabs [hi,hi,lo]
__device__ __align__(16) __nv_bfloat16 g_bs[(size_t)3 * EMB * K2];   // B'_z [768 n][2304 k] slabs [hi,lo,hi]

// ---------------------------------------------------------------------------
// PTX helpers — tcgen05 only under the sm_103a feature guard.
// ---------------------------------------------------------------------------
__device__ __forceinline__ uint32_t smem_u32(const void* p) {
    uint32_t a;
    asm("{ .reg .u64 t; cvta.to.shared.u64 t, %1; cvt.u32.u64 %0, t; }" : "=r"(a) : "l"(p));
    return a;
}
__device__ __forceinline__ uint32_t elect_one() {
    uint32_t pred;
    asm volatile("{\n\t.reg .pred p;\n\telect.sync _|p, 0xFFFFFFFF;\n\tselp.b32 %0, 1, 0, p;\n\t}" : "=r"(pred));
    return pred;
}
__device__ __forceinline__ void mbar_init(uint32_t mb, uint32_t cnt) {
    asm volatile("mbarrier.init.shared.b64 [%0], %1;" :: "r"(mb), "r"(cnt) : "memory");
}
__device__ __forceinline__ void mbar_wait(uint32_t mb, uint32_t phase) {
    asm volatile(
        "{\n\t.reg .pred P1;\n\t"
        "WL_%=:\n\t"
        "mbarrier.try_wait.parity.acquire.cta.shared::cta.b64 P1, [%0], %1, 0x989680;\n\t"
        "@P1 bra.uni WD_%=;\n\t"
        "bra.uni WL_%=;\n\t"
        "WD_%=:\n\t}"
        :: "r"(mb), "r"(phase) : "memory");
}

#if defined(__CUDA_ARCH_FEAT_SM103_ALL)
#define TC_OK 1
#else
#define TC_OK 0
#endif

#if TC_OK
__device__ __forceinline__ void mma_f16_ss(uint32_t d, uint64_t a, uint64_t b,
                                           uint32_t idesc, bool acc) {
    uint32_t en = acc ? 1u : 0u;
    asm volatile(
        "{\n\t.reg .pred p;\n\tsetp.ne.u32 p, %5, 0;\n\t"
        "tcgen05.mma.cta_group::1.kind::f16 [%0], %1, %2, %3, {%4, %4, %4, %4}, p;\n\t}"
        :: "r"(d), "l"(a), "l"(b), "r"(idesc), "r"(0u), "r"(en) : "memory");
}
__device__ __forceinline__ void tc_commit(uint32_t mb) {
    asm volatile("tcgen05.commit.cta_group::1.mbarrier::arrive::one.shared::cluster.b64 [%0];"
                 :: "r"(mb) : "memory");
}
#define TC_LD_X32(r, addr) \
    asm volatile( \
        "tcgen05.ld.sync.aligned.32x32b.x32.b32 " \
        "{%0, %1, %2, %3, %4, %5, %6, %7, " \
        " %8, %9, %10, %11, %12, %13, %14, %15, " \
        " %16, %17, %18, %19, %20, %21, %22, %23, " \
        " %24, %25, %26, %27, %28, %29, %30, %31}, [%32];" \
        : "=r"((r)[0]),  "=r"((r)[1]),  "=r"((r)[2]),  "=r"((r)[3]), \
          "=r"((r)[4]),  "=r"((r)[5]),  "=r"((r)[6]),  "=r"((r)[7]), \
          "=r"((r)[8]),  "=r"((r)[9]),  "=r"((r)[10]), "=r"((r)[11]), \
          "=r"((r)[12]), "=r"((r)[13]), "=r"((r)[14]), "=r"((r)[15]), \
          "=r"((r)[16]), "=r"((r)[17]), "=r"((r)[18]), "=r"((r)[19]), \
          "=r"((r)[20]), "=r"((r)[21]), "=r"((r)[22]), "=r"((r)[23]), \
          "=r"((r)[24]), "=r"((r)[25]), "=r"((r)[26]), "=r"((r)[27]), \
          "=r"((r)[28]), "=r"((r)[29]), "=r"((r)[30]), "=r"((r)[31]) \
        : "r"(addr))
#endif

static __device__ __forceinline__ uint64_t make_desc(uint32_t addr) {
    const uint64_t base = (2ull << 61) | (1ull << 46) | (64ull << 32) | (1ull << 16);
    return base | ((uint64_t)(addr >> 4) & 0x3FFF);
}
static __device__ __forceinline__ uint32_t sw128(uint32_t off) {
    return off ^ ((off >> 3) & 0x70);
}
static __device__ __forceinline__ uint32_t pack_bf2(float a, float b) {
    __nv_bfloat162 t = __floats2bfloat162_rn(a, b);
    return *(uint32_t*)&t;
}

// ---------------------------------------------------------------------------
// Split pre-pass: hs -> g_as (slabs hi,hi,lo)
// ---------------------------------------------------------------------------
__global__ void split_hs_kernel(const float* __restrict__ hs)
{
    int i = blockIdx.x * 256 + threadIdx.x;
    float x = hs[i];
    __nv_bfloat16 h = __float2bfloat16(x);
    __nv_bfloat16 l = __float2bfloat16(x - __bfloat162float(h));
    int row = i / EMB, k = i - row * EMB;
    __nv_bfloat16* p = &g_as[(size_t)row * K2];
    p[k] = h; p[EMB + k] = h; p[2 * EMB + k] = l;
}

__global__ void split_w_kernel(const float* __restrict__ Wq,
                               const float* __restrict__ Wk,
                               const float* __restrict__ Wv)
{
    __shared__ float t[32][33];
    const int z = blockIdx.z;
    const float* W = (z == 0) ? Wq : (z == 1) ? Wk : Wv;
    int k = blockIdx.y * 32 + threadIdx.y;
    int n = blockIdx.x * 32 + threadIdx.x;
    t[threadIdx.y][threadIdx.x] = W[(size_t)k * EMB + n];
    __syncthreads();
    int nn = blockIdx.x * 32 + threadIdx.y;
    int kk = blockIdx.y * 32 + threadIdx.x;
    float x = t[threadIdx.x][threadIdx.y];
    __nv_bfloat16 h = __float2bfloat16(x);
    __nv_bfloat16 l = __float2bfloat16(x - __bfloat162float(h));
    __nv_bfloat16* p = &g_bs[((size_t)z * EMB + nn) * K2];
    p[kk] = h; p[EMB + kk] = l; p[2 * EMB + kk] = h;
}

// ---------------------------------------------------------------------------
// QKV GEMM on tcgen05 (validated). Epilogues:
//   z==0: Q fp32 scaled, [NH][SQ][HD]
//   z==1: K bf16 hi/lo split, [NH][SQ][HD]
//   z==2: V bf16 hi/lo split, TRANSPOSED [NH][HD][SQ]
// ---------------------------------------------------------------------------
#define STAGE_BYTES 49152
#define QKV_SMEM (2 * STAGE_BYTES + 32)
#define QKV_IDESC 0x8400490u

__global__ __launch_bounds__(256) void qkv_mma_kernel(
    const float* __restrict__ bq, const float* __restrict__ bk,
    const float* __restrict__ bv)
{
    const int z = blockIdx.z;
    const float* bias = (z == 0) ? bq : (z == 1) ? bk : bv;
    const int n0 = blockIdx.x * 256;
    const int m0 = blockIdx.y * 128;
    const int tid = threadIdx.x;

#if TC_OK
    extern __shared__ __align__(1024) char sm[];
    const uint32_t sb = smem_u32(sm);
    const int wid = tid >> 5, lid = tid & 31;

    const uint32_t ctrl = sb + 2 * STAGE_BYTES;
    const uint32_t mb[2] = { sb + 2 * STAGE_BYTES + 8, sb + 2 * STAGE_BYTES + 16 };

    if (tid == 0) { mbar_init(mb[0], 1); mbar_init(mb[1], 1); }
    if (wid == 0) {
        asm volatile("tcgen05.alloc.cta_group::1.sync.aligned.shared::cta.b32 [%0], %1;"
                     :: "r"(ctrl), "r"(256u) : "memory");
        asm volatile("tcgen05.relinquish_alloc_permit.cta_group::1.sync.aligned;");
    }
    __syncthreads();
    uint32_t tmem;
    asm volatile("ld.shared.b32 %0, [%1];" : "=r"(tmem) : "r"(ctrl));

    const __nv_bfloat16* Arow = &g_as[(size_t)m0 * K2];
    const __nv_bfloat16* Brow = &g_bs[((size_t)z * EMB + n0) * K2];

    int ph[2] = { 0, 0 };

    for (int c = 0; c < 36; c++) {
        const int s = c & 1;
        if (c >= 2) { mbar_wait(mb[s], ph[s]); ph[s] ^= 1; }
        const int kk = c * 64;
        char* stA = sm + s * STAGE_BYTES;
        char* stB = stA + 16384;

        #pragma unroll
        for (int j = 0; j < 4; j++) {
            int cid = tid + j * 256;
            int r = cid >> 3, c16 = cid & 7;
            uint32_t off = sw128((uint32_t)(r * 128 + c16 * 16));
            *(uint4*)(stA + off) = *(const uint4*)(Arow + (size_t)r * K2 + kk + c16 * 8);
        }
        #pragma unroll
        for (int j = 0; j < 8; j++) {
            int cid = tid + j * 256;
            int r = cid >> 3, c16 = cid & 7;
            uint32_t off = sw128((uint32_t)(r * 128 + c16 * 16));
            *(uint4*)(stB + off) = *(const uint4*)(Brow + (size_t)r * K2 + kk + c16 * 8);
        }
        asm volatile("fence.proxy.async.shared::cta;" ::: "memory");
        __syncthreads();

        if (wid == 0) {
            if (elect_one()) {
                uint64_t da = make_desc(sb + s * STAGE_BYTES);
                uint64_t db = make_desc(sb + s * STAGE_BYTES + 16384);
                #pragma unroll
                for (int k = 0; k < 4; k++)
                    mma_f16_ss(tmem, da + k * 2, db + k * 2, QKV_IDESC, (c > 0) || (k > 0));
                tc_commit(mb[s]);
            }
        }
    }

    mbar_wait(mb[1], ph[1]);
    asm volatile("tcgen05.fence::after_thread_sync;" ::: "memory");

    if (wid < 4) {
        const int r = wid * 32 + lid;
        #pragma unroll
        for (int cb = 0; cb < 8; cb++) {
            uint32_t dr[32];
            TC_LD_X32(dr, tmem + cb * 32);
            asm volatile("tcgen05.wait::ld.sync.aligned;" ::: "memory");
            const int nbase = n0 + cb * 32;
            const int head = nbase >> 6;
            if (z == 0) {
                float* op = &g_q[((size_t)head * SQ + m0 + r) * HD + (nbase & 63)];
                #pragma unroll
                for (int q = 0; q < 32; q += 4) {
                    float4 v;
                    v.x = (__uint_as_float(dr[q + 0]) + bias[nbase + q + 0]) * 0.125f;
                    v.y = (__uint_as_float(dr[q + 1]) + bias[nbase + q + 1]) * 0.125f;
                    v.z = (__uint_as_float(dr[q + 2]) + bias[nbase + q + 2]) * 0.125f;
                    v.w = (__uint_as_float(dr[q + 3]) + bias[nbase + q + 3]) * 0.125f;
                    *(float4*)&op[q] = v;
                }
            } else if (z == 1) {
                uint32_t hw[16], lw[16];
                #pragma unroll
                for (int q = 0; q < 32; q += 2) {
                    float v0 = __uint_as_float(dr[q + 0]) + bias[nbase + q + 0];
                    float v1 = __uint_as_float(dr[q + 1]) + bias[nbase + q + 1];
                    float h0 = __bfloat162float(__float2bfloat16(v0));
                    float h1 = __bfloat162float(__float2bfloat16(v1));
                    hw[q >> 1] = pack_bf2(h0, h1);
                    lw[q >> 1] = pack_bf2(v0 - h0, v1 - h1);
                }
                size_t base = ((size_t)head * SQ + m0 + r) * HD + (nbase & 63);
                #pragma unroll
                for (int q = 0; q < 4; q++) {
                    *(uint4*)&g_khi[base + q * 8] = *(uint4*)&hw[q * 4];
                    *(uint4*)&g_klo[base + q * 8] = *(uint4*)&lw[q * 4];
                }
            } else {
                #pragma unroll
                for (int q = 0; q < 32; q++) {
                    float v = __uint_as_float(dr[q]) + bias[nbase + q];
                    __nv_bfloat16 hb = __float2bfloat16(v);
                    __nv_bfloat16 lb = __float2bfloat16(v - __bfloat162float(hb));
                    size_t idx = ((size_t)head * HD + (nbase & 63) + q) * SQ + m0 + r;
                    g_vthi[idx] = hb;
                    g_vtlo[idx] = lb;
                }
            }
        }
    }
    __syncthreads();
    if (wid == 0) {
        asm volatile("tcgen05.dealloc.cta_group::1.sync.aligned.b32 %0, %1;"
                     :: "r"(tmem), "r"(256u));
    }
#else
    const int r = tid >> 1;
    const int cb0 = (tid & 1) * 128;
    for (int cc = 0; cc < 128; cc++) {
        const int n = n0 + cb0 + cc;
        const __nv_bfloat16* a = &g_as[(size_t)(m0 + r) * K2];
        const __nv_bfloat16* b = &g_bs[((size_t)z * EMB + n) * K2];
        float acc = 0.0f;
        for (int k = 0; k < K2; k++)
            acc += __bfloat162float(a[k]) * __bfloat162float(b[k]);
        const int head = n >> 6;
        float v = acc + bias[n];
        if (z == 0) {
            g_q[((size_t)head * SQ + m0 + r) * HD + (n & 63)] = v * 0.125f;
        } else if (z == 1) {
            __nv_bfloat16 hb = __float2bfloat16(v);
            __nv_bfloat16 lb = __float2bfloat16(v - __bfloat162float(hb));
            size_t idx = ((size_t)head * SQ + m0 + r) * HD + (n & 63);
            g_khi[idx] = hb; g_klo[idx] = lb;
        } else {
            __nv_bfloat16 hb = __float2bfloat16(v);
            __nv_bfloat16 lb = __float2bfloat16(v - __bfloat162float(hb));
            size_t idx = ((size_t)head * HD + (n & 63)) * SQ + m0 + r;
            g_vthi[idx] = hb; g_vtlo[idx] = lb;
        }
    }
#endif
}

// ---------------------------------------------------------------------------
// Banded attention on tcgen05. Per CTA = (head, 128 queries), block = 256.
// K/V pre-split bf16 in global (V also pre-transposed): staging = pure copies.
// K(t+1) register-prefetched BEFORE the mbS wait. Recycled-K pipelining.
// smem 97.6KB -> 2 CTA/SM. TMEM: S @0 (64), O @64 (64); alloc 128.
// ---------------------------------------------------------------------------
#define AT_QHI   0          // 16KB
#define AT_QLO   16384      // 16KB
#define AT_KHI   32768      // 8KB
#define AT_KLO   40960      // 8KB
#define AT_VTHI  49152      // 8KB
#define AT_VTLO  57344      // 8KB
#define AT_PHI   65536      // 16KB
#define AT_PLO   81920      // 16KB
#define AT_KMSK  98304      // 2 x 64 floats
#define AT_LSUM  98816      // 2 x 128 floats
#define AT_CTRL  99840
#define AT_MBS   99848
#define AT_MBO   99856
#define AT_SMEM  99904
#define ATT_IDESC 0x8100490u   // f32 acc, bf16 a/b, N=64, M=128

__global__ __launch_bounds__(256, 2) void attn_mma_kernel(
    const float* __restrict__ amask,
    const unsigned char* __restrict__ qmask,
    float* __restrict__ out)
{
    const int h  = blockIdx.y;
    const int q0 = blockIdx.x * 128;
    const int tid = threadIdx.x;

#if TC_OK
    extern __shared__ __align__(1024) char sm[];
    const uint32_t sb = smem_u32(sm);
    const int wid = tid >> 5, lane = tid & 31;
    const int wg = wid >> 2;                    // warpgroup 0/1 -> col half
    const int wrow = (wid & 3) * 32 + lane;     // query row 0..127
    const int jc0 = wg * 32;                    // this WG's 32-col window
    const uint32_t mbS = sb + AT_MBS, mbO = sb + AT_MBO;
    float* kmsk = (float*)(sm + AT_KMSK);
    float* lsum = (float*)(sm + AT_LSUM);

    if (tid == 0) { mbar_init(mbS, 1); mbar_init(mbO, 1); }
    if (wid == 0) {
        asm volatile("tcgen05.alloc.cta_group::1.sync.aligned.shared::cta.b32 [%0], %1;"
                     :: "r"(sb + AT_CTRL), "r"(128u) : "memory");
        asm volatile("tcgen05.relinquish_alloc_permit.cta_group::1.sync.aligned;");
    }
    __syncthreads();
    uint32_t tmem;
    asm volatile("ld.shared.b32 %0, [%1];" : "=r"(tmem) : "r"(sb + AT_CTRL));
    const uint32_t TM_S = tmem, TM_O = tmem + 64;

    const int gi = q0 + wrow;

    // per-thread staging coordinates (4 threads per 64-wide row)
    const int rk = tid >> 2, qs = (tid & 3) * 16;          // K: row, 16-elem seg
    const uint32_t ko0 = sw128((uint32_t)(rk * 128 + qs * 2));
    const uint32_t ko1 = sw128((uint32_t)(rk * 128 + qs * 2 + 16));

    // ---- Prologue: Q tile -> Qhi/Qlo bf16 swizzled (2 threads per row) ----
    {
        const int r = tid >> 1, hf = (tid & 1) * 32;
        const float* qp = &g_q[((size_t)h * SQ + q0 + r) * HD + hf];
        float f[32];
        #pragma unroll
        for (int i = 0; i < 8; i++) *(float4*)&f[i * 4] = *(const float4*)&qp[i * 4];
        #pragma unroll
        for (int g = 0; g < 4; g++) {
            uint32_t off = sw128((uint32_t)(r * 128 + (hf + g * 8) * 2));
            uint4 hv, lv;
            #pragma unroll
            for (int e = 0; e < 8; e += 2) {
                float x0 = f[g * 8 + e], x1 = f[g * 8 + e + 1];
                float h0 = __bfloat162float(__float2bfloat16(x0));
                float h1 = __bfloat162float(__float2bfloat16(x1));
                ((uint32_t*)&hv)[e >> 1] = pack_bf2(h0, h1);
                ((uint32_t*)&lv)[e >> 1] = pack_bf2(x0 - h0, x1 - h1);
            }
            *(uint4*)(sm + AT_QHI + off) = hv;
            *(uint4*)(sm + AT_QLO + off) = lv;
        }
    }

    // valid band tiles
    int jbs[10]; int nt = 0;
    #pragma unroll
    for (int t = 0; t < 10; t++) {
        int jb = q0 - 256 + t * 64;
        if (jb >= 0 && jb < SQ) jbs[nt++] = jb;
    }

    const uint64_t dQh = make_desc(sb + AT_QHI), dQl = make_desc(sb + AT_QLO);
    const uint64_t dKh = make_desc(sb + AT_KHI), dKl = make_desc(sb + AT_KLO);
    const uint64_t dVh = make_desc(sb + AT_VTHI), dVl = make_desc(sb + AT_VTLO);
    const uint64_t dPh = make_desc(sb + AT_PHI), dPl = make_desc(sb + AT_PLO);

    auto issue_S = [&]() {
        asm volatile("tcgen05.fence::after_thread_sync;" ::: "memory");
        #pragma unroll
        for (int k = 0; k < 4; k++) mma_f16_ss(TM_S, dQh + k * 2, dKh + k * 2, ATT_IDESC, k > 0);
        #pragma unroll
        for (int k = 0; k < 4; k++) mma_f16_ss(TM_S, dQh + k * 2, dKl + k * 2, ATT_IDESC, true);
        #pragma unroll
        for (int k = 0; k < 4; k++) mma_f16_ss(TM_S, dQl + k * 2, dKh + k * 2, ATT_IDESC, true);
        tc_commit(mbS);
    };

    float l_part = 0.0f;
    int phS = 0, phO = 0;

    // ---- Prologue: stage K(0), issue S(0) ----
    {
        const __nv_bfloat16* kh = &g_khi[((size_t)h * SQ + jbs[0] + rk) * HD + qs];
        const __nv_bfloat16* kl = &g_klo[((size_t)h * SQ + jbs[0] + rk) * HD + qs];
        *(uint4*)(sm + AT_KHI + ko0) = *(const uint4*)kh;
        *(uint4*)(sm + AT_KHI + ko1) = *(const uint4*)(kh + 8);
        *(uint4*)(sm + AT_KLO + ko0) = *(const uint4*)kl;
        *(uint4*)(sm + AT_KLO + ko1) = *(const uint4*)(kl + 8);
        if (tid < 64)
            kmsk[tid] = (amask[jbs[0] + tid] != 0.0f) ? -1e8f : 0.0f;
    }
    asm volatile("fence.proxy.async.shared::cta;" ::: "memory");
    __syncthreads();
    if (wid == 0 && elect_one()) issue_S();

    for (int it = 0; it < nt; it++) {
        const int b = it & 1;
        const bool more = (it + 1 < nt);
        const int jb = jbs[it];

        // ---- prefetch K(t+1) + kmsk(t+1) into regs BEFORE the S(t) wait ----
        uint4 ka0, ka1, kb0, kb1;
        float km = 0.0f;
        if (more) {
            const __nv_bfloat16* kh = &g_khi[((size_t)h * SQ + jbs[it + 1] + rk) * HD + qs];
            const __nv_bfloat16* kl = &g_klo[((size_t)h * SQ + jbs[it + 1] + rk) * HD + qs];
            ka0 = *(const uint4*)kh; ka1 = *(const uint4*)(kh + 8);
            kb0 = *(const uint4*)kl; kb1 = *(const uint4*)(kl + 8);
            if (tid < 64)
                km = (amask[jbs[it + 1] + tid] != 0.0f) ? -1e8f : 0.0f;
        }

        // ---- wait S(t), read scores ----
        mbar_wait(mbS, phS); phS ^= 1;
        asm volatile("tcgen05.fence::after_thread_sync;" ::: "memory");
        uint32_t s0[32];
        TC_LD_X32(s0, TM_S + jc0);
        asm volatile("tcgen05.wait::ld.sync.aligned;" ::: "memory");
        asm volatile("tcgen05.fence::before_thread_sync;" ::: "memory");

        // ---- K smem free: store K(t+1), issue S(t+1) (overlaps softmax) ----
        if (more) {
            *(uint4*)(sm + AT_KHI + ko0) = ka0;
            *(uint4*)(sm + AT_KHI + ko1) = ka1;
            *(uint4*)(sm + AT_KLO + ko0) = kb0;
            *(uint4*)(sm + AT_KLO + ko1) = kb1;
            if (tid < 64) kmsk[(b ^ 1) * 64 + tid] = km;
        }
        asm volatile("fence.proxy.async.shared::cta;" ::: "memory");
        __syncthreads();
        if (more && wid == 0 && elect_one()) issue_S();

        // ---- softmax on this WG's 32-col half ----
        float p[32];
        float rs = 0.0f;
        #pragma unroll
        for (int j = 0; j < 32; j++) {
            const int diff = gi - (jb + jc0 + j);
            const bool valid = (diff <= WIN) && (diff >= -WIN);
            float sv = __uint_as_float(s0[j]) + kmsk[b * 64 + jc0 + j];
            float pv = valid ? __expf(sv) : 0.0f;
            p[j] = pv;
            rs += pv;
        }
        l_part += rs;

        // ---- load Vt(t) (pre-split, pre-transposed) ----
        uint4 va0, va1, vb0, vb1;
        {
            const __nv_bfloat16* vh = &g_vthi[((size_t)h * HD + rk) * SQ + jb + qs];
            const __nv_bfloat16* vl = &g_vtlo[((size_t)h * HD + rk) * SQ + jb + qs];
            va0 = *(const uint4*)vh; va1 = *(const uint4*)(vh + 8);
            vb0 = *(const uint4*)vl; vb1 = *(const uint4*)(vl + 8);
        }

        // PV(t-1) must be complete before Vt/P overwrite
        if (it > 0) { mbar_wait(mbO, phO); phO ^= 1; }

        // ---- store Vt ----
        *(uint4*)(sm + AT_VTHI + ko0) = va0;
        *(uint4*)(sm + AT_VTHI + ko1) = va1;
        *(uint4*)(sm + AT_VTLO + ko0) = vb0;
        *(uint4*)(sm + AT_VTLO + ko1) = vb1;

        // ---- store P hi/lo (row wrow, cols jc0..jc0+31) ----
        #pragma unroll
        for (int g = 0; g < 4; g++) {
            uint32_t off = sw128((uint32_t)(wrow * 128 + (jc0 + g * 8) * 2));
            uint4 hv, lv;
            #pragma unroll
            for (int e = 0; e < 8; e += 2) {
                float x0 = p[g * 8 + e], x1 = p[g * 8 + e + 1];
                float h0 = __bfloat162float(__float2bfloat16(x0));
                float h1 = __bfloat162float(__float2bfloat16(x1));
                ((uint32_t*)&hv)[e >> 1] = pack_bf2(h0, h1);
                ((uint32_t*)&lv)[e >> 1] = pack_bf2(x0 - h0, x1 - h1);
            }
            *(uint4*)(sm + AT_PHI + off) = hv;
            *(uint4*)(sm + AT_PLO + off) = lv;
        }
        asm volatile("fence.proxy.async.shared::cta;" ::: "memory");
        __syncthreads();

        // ---- O += P.V (3-term split) ----
        if (wid == 0 && elect_one()) {
            asm volatile("tcgen05.fence::after_thread_sync;" ::: "memory");
            #pragma unroll
            for (int k = 0; k < 4; k++) mma_f16_ss(TM_O, dPh + k * 2, dVh + k * 2, ATT_IDESC, !(it == 0 && k == 0));
            #pragma unroll
            for (int k = 0; k < 4; k++) mma_f16_ss(TM_O, dPh + k * 2, dVl + k * 2, ATT_IDESC, true);
            #pragma unroll
            for (int k = 0; k < 4; k++) mma_f16_ss(TM_O, dPl + k * 2, dVh + k * 2, ATT_IDESC, true);
            tc_commit(mbO);
        }
    }

    // ---- Epilogue: reduce l across WG halves, normalize, write out ----
    lsum[wg * 128 + wrow] = l_part;
    mbar_wait(mbO, phO);
    asm volatile("tcgen05.fence::after_thread_sync;" ::: "memory");
    __syncthreads();
    {
        uint32_t o0[32];
        TC_LD_X32(o0, TM_O + jc0);
        asm volatile("tcgen05.wait::ld.sync.aligned;" ::: "memory");
        const float l_i = lsum[wrow] + lsum[128 + wrow];
        const float inv = (qmask[gi] != 0) ? 0.0f : 1.0f / l_i;
        float* op = &out[(size_t)gi * EMB + h * HD + jc0];
        #pragma unroll
        for (int j = 0; j < 32; j += 4) {
            float4 v;
            v.x = __uint_as_float(o0[j + 0]) * inv;
            v.y = __uint_as_float(o0[j + 1]) * inv;
            v.z = __uint_as_float(o0[j + 2]) * inv;
            v.w = __uint_as_float(o0[j + 3]) * inv;
            *(float4*)&op[j] = v;
        }
    }
    __syncthreads();
    if (wid == 0) {
        asm volatile("tcgen05.dealloc.cta_group::1.sync.aligned.b32 %0, %1;"
                     :: "r"(tmem), "r"(128u));
    }
#else
    // Generic fallback (compute_103 PTX pass only; never runs on GB300).
    if (tid < 128) {
        const int gi = q0 + tid;
        const float* qp = &g_q[((size_t)h * SQ + gi) * HD];
        float l = 0.0f, O[64];
        #pragma unroll
        for (int d = 0; d < 64; d++) O[d] = 0.0f;
        int lo = gi - WIN; if (lo < 0) lo = 0;
        int hi = gi + WIN; if (hi > SQ - 1) hi = SQ - 1;
        for (int gj = lo; gj <= hi; gj++) {
            float s = 0.0f;
            for (int d = 0; d < 64; d++) {
                float kd = __bfloat162float(g_khi[((size_t)h * SQ + gj) * HD + d])
                         + __bfloat162float(g_klo[((size_t)h * SQ + gj) * HD + d]);
                s += qp[d] * kd;
            }
            s += (amask[gj] != 0.0f) ? -1e8f : 0.0f;
            float pv = __expf(s);
            l += pv;
            for (int d = 0; d < 64; d++) {
                float vd = __bfloat162float(g_vthi[((size_t)h * HD + d) * SQ + gj])
                         + __bfloat162float(g_vtlo[((size_t)h * HD + d) * SQ + gj]);
                O[d] += pv * vd;
            }
        }
        const float inv = (qmask[gi] != 0) ? 0.0f : 1.0f / l;
        float* op = &out[(size_t)gi * EMB + h * HD];
        for (int d = 0; d < 64; d++) op[d] = O[d] * inv;
    }
#endif
}

// ---------------------------------------------------------------------------
// Launch
// ---------------------------------------------------------------------------
extern "C" void kernel_launch(void* const* d_in, const int* in_sizes, int n_in,
                              void* d_out, int out_size)
{
    const float* hs            = (const float*)d_in[0];
    const float* amask         = (const float*)d_in[1];
    const unsigned char* qmask = (const unsigned char*)d_in[2];
    const float* Wq = (const float*)d_in[3];
    const float* bq = (const float*)d_in[4];
    const float* Wk = (const float*)d_in[5];
    const float* bk = (const float*)d_in[6];
    const float* Wv = (const float*)d_in[7];
    const float* bv = (const float*)d_in[8];
    float* out = (float*)d_out;

    split_hs_kernel<<<(SQ * EMB) / 256, 256>>>(hs);
    split_w_kernel<<<dim3(EMB / 32, EMB / 32, 3), dim3(32, 32)>>>(Wq, Wk, Wv);

    cudaFuncSetAttribute(qkv_mma_kernel,
                         cudaFuncAttributeMaxDynamicSharedMemorySize, QKV_SMEM);
    qkv_mma_kernel<<<dim3(EMB / 256, SQ / 128, 3), 256, QKV_SMEM>>>(bq, bk, bv);

    cudaFuncSetAttribute(attn_mma_kernel,
                         cudaFuncAttributeMaxDynamicSharedMemorySize, AT_SMEM);
    attn_mma_kernel<<<dim3(SQ / 128, NH), 256, AT_SMEM>>>(amask, qmask, out);
}

// round 15
// speedup vs baseline: 1.7642x; 1.0524x over previous
#include <cuda_runtime.h>
#include <cuda_bf16.h>
#include <math.h>
#include <stdint.h>

// Problem constants
#define SQ   4096
#define EMB  768
#define NH   12
#define HD   64
#define WIN  256
#define K2   2304   // 3 * 768 split-GEMM depth

// Scratch (allocation-free rule: __device__ globals)
// K stored pre-split: g_khi/g_klo [NH][SQ][HD] bf16
// V stored pre-split AND pre-transposed: g_vthi/g_vtlo [NH][HD][SQ] bf16
__device__ float g_q[NH * SQ * HD];
__device__ __align__(16) __nv_bfloat16 g_khi[NH * SQ * HD];
__device__ __align__(16) __nv_bfloat16 g_klo[NH * SQ * HD];
__device__ __align__(16) __nv_bfloat16 g_vthi[NH * HD * SQ];
__device__ __align__(16) __nv_bfloat16 g_vtlo[NH * HD * SQ];
__device__ __align__(16) __nv_bfloat16 g_as[(size_t)SQ * K2];        // A' [4096][2304] slabs [hi,hi,lo]
__device__ __align__(16) __nv_bfloat16 g_bs[(size_t)3 * EMB * K2];   // B'_z [768 n][2304 k] slabs [hi,lo,hi]

// ---------------------------------------------------------------------------
// PTX helpers — tcgen05 only under the sm_103a feature guard.
// ---------------------------------------------------------------------------
__device__ __forceinline__ uint32_t smem_u32(const void* p) {
    uint32_t a;
    asm("{ .reg .u64 t; cvta.to.shared.u64 t, %1; cvt.u32.u64 %0, t; }" : "=r"(a) : "l"(p));
    return a;
}
__device__ __forceinline__ uint32_t elect_one() {
    uint32_t pred;
    asm volatile("{\n\t.reg .pred p;\n\telect.sync _|p, 0xFFFFFFFF;\n\tselp.b32 %0, 1, 0, p;\n\t}" : "=r"(pred));
    return pred;
}
__device__ __forceinline__ void mbar_init(uint32_t mb, uint32_t cnt) {
    asm volatile("mbarrier.init.shared.b64 [%0], %1;" :: "r"(mb), "r"(cnt) : "memory");
}
__device__ __forceinline__ void mbar_wait(uint32_t mb, uint32_t phase) {
    asm volatile(
        "{\n\t.reg .pred P1;\n\t"
        "WL_%=:\n\t"
        "mbarrier.try_wait.parity.acquire.cta.shared::cta.b64 P1, [%0], %1, 0x989680;\n\t"
        "@P1 bra.uni WD_%=;\n\t"
        "bra.uni WL_%=;\n\t"
        "WD_%=:\n\t}"
        :: "r"(mb), "r"(phase) : "memory");
}

#if defined(__CUDA_ARCH_FEAT_SM103_ALL)
#define TC_OK 1
#else
#define TC_OK 0
#endif

#if TC_OK
__device__ __forceinline__ void mma_f16_ss(uint32_t d, uint64_t a, uint64_t b,
                                           uint32_t idesc, bool acc) {
    uint32_t en = acc ? 1u : 0u;
    asm volatile(
        "{\n\t.reg .pred p;\n\tsetp.ne.u32 p, %5, 0;\n\t"
        "tcgen05.mma.cta_group::1.kind::f16 [%0], %1, %2, %3, {%4, %4, %4, %4}, p;\n\t}"
        :: "r"(d), "l"(a), "l"(b), "r"(idesc), "r"(0u), "r"(en) : "memory");
}
__device__ __forceinline__ void tc_commit(uint32_t mb) {
    asm volatile("tcgen05.commit.cta_group::1.mbarrier::arrive::one.shared::cluster.b64 [%0];"
                 :: "r"(mb) : "memory");
}
#define TC_LD_X32(r, addr) \
    asm volatile( \
        "tcgen05.ld.sync.aligned.32x32b.x32.b32 " \
        "{%0, %1, %2, %3, %4, %5, %6, %7, " \
        " %8, %9, %10, %11, %12, %13, %14, %15, " \
        " %16, %17, %18, %19, %20, %21, %22, %23, " \
        " %24, %25, %26, %27, %28, %29, %30, %31}, [%32];" \
        : "=r"((r)[0]),  "=r"((r)[1]),  "=r"((r)[2]),  "=r"((r)[3]), \
          "=r"((r)[4]),  "=r"((r)[5]),  "=r"((r)[6]),  "=r"((r)[7]), \
          "=r"((r)[8]),  "=r"((r)[9]),  "=r"((r)[10]), "=r"((r)[11]), \
          "=r"((r)[12]), "=r"((r)[13]), "=r"((r)[14]), "=r"((r)[15]), \
          "=r"((r)[16]), "=r"((r)[17]), "=r"((r)[18]), "=r"((r)[19]), \
          "=r"((r)[20]), "=r"((r)[21]), "=r"((r)[22]), "=r"((r)[23]), \
          "=r"((r)[24]), "=r"((r)[25]), "=r"((r)[26]), "=r"((r)[27]), \
          "=r"((r)[28]), "=r"((r)[29]), "=r"((r)[30]), "=r"((r)[31]) \
        : "r"(addr))
#endif

static __device__ __forceinline__ uint64_t make_desc(uint32_t addr) {
    const uint64_t base = (2ull << 61) | (1ull << 46) | (64ull << 32) | (1ull << 16);
    return base | ((uint64_t)(addr >> 4) & 0x3FFF);
}
static __device__ __forceinline__ uint32_t sw128(uint32_t off) {
    return off ^ ((off >> 3) & 0x70);
}
static __device__ __forceinline__ uint32_t pack_bf2(float a, float b) {
    __nv_bfloat162 t = __floats2bfloat162_rn(a, b);
    return *(uint32_t*)&t;
}

// ---------------------------------------------------------------------------
// Split pre-pass: hs -> g_as (slabs hi,hi,lo). Vectorized: 4 elems/thread.
// ---------------------------------------------------------------------------
__global__ void split_hs_kernel(const float* __restrict__ hs)
{
    int i4 = blockIdx.x * 256 + threadIdx.x;       // over (4096*768)/4
    float4 x = ((const float4*)hs)[i4];
    int row = i4 / (EMB / 4), kq = (i4 % (EMB / 4)) * 4;
    float h0 = __bfloat162float(__float2bfloat16(x.x));
    float h1 = __bfloat162float(__float2bfloat16(x.y));
    float h2 = __bfloat162float(__float2bfloat16(x.z));
    float h3 = __bfloat162float(__float2bfloat16(x.w));
    uint2 hv = { pack_bf2(h0, h1), pack_bf2(h2, h3) };
    uint2 lv = { pack_bf2(x.x - h0, x.y - h1), pack_bf2(x.z - h2, x.w - h3) };
    __nv_bfloat16* p = &g_as[(size_t)row * K2];
    *(uint2*)&p[kq] = hv;
    *(uint2*)&p[EMB + kq] = hv;
    *(uint2*)&p[2 * EMB + kq] = lv;
}

__global__ void split_w_kernel(const float* __restrict__ Wq,
                               const float* __restrict__ Wk,
                               const float* __restrict__ Wv)
{
    __shared__ float t[32][33];
    const int z = blockIdx.z;
    const float* W = (z == 0) ? Wq : (z == 1) ? Wk : Wv;
    int k = blockIdx.y * 32 + threadIdx.y;
    int n = blockIdx.x * 32 + threadIdx.x;
    t[threadIdx.y][threadIdx.x] = W[(size_t)k * EMB + n];
    __syncthreads();
    int nn = blockIdx.x * 32 + threadIdx.y;
    int kk = blockIdx.y * 32 + threadIdx.x;
    float x = t[threadIdx.x][threadIdx.y];
    __nv_bfloat16 h = __float2bfloat16(x);
    __nv_bfloat16 l = __float2bfloat16(x - __bfloat162float(h));
    __nv_bfloat16* p = &g_bs[((size_t)z * EMB + nn) * K2];
    p[kk] = h; p[EMB + kk] = l; p[2 * EMB + kk] = h;
}

// ---------------------------------------------------------------------------
// QKV GEMM on tcgen05. Register-prefetched staging: chunk c+1's global loads
// issue BEFORE the stage wait / chunk c's smem stores, hiding LDG latency.
// Epilogues: z==0 Q fp32; z==1 K bf16-split; z==2 V bf16-split transposed.
// ---------------------------------------------------------------------------
#define STAGE_BYTES 49152
#define QKV_SMEM (2 * STAGE_BYTES + 32)
#define QKV_IDESC 0x8400490u

__global__ __launch_bounds__(256, 2) void qkv_mma_kernel(
    const float* __restrict__ bq, const float* __restrict__ bk,
    const float* __restrict__ bv)
{
    const int z = blockIdx.z;
    const float* bias = (z == 0) ? bq : (z == 1) ? bk : bv;
    const int n0 = blockIdx.x * 256;
    const int m0 = blockIdx.y * 128;
    const int tid = threadIdx.x;

#if TC_OK
    extern __shared__ __align__(1024) char sm[];
    const uint32_t sb = smem_u32(sm);
    const int wid = tid >> 5, lid = tid & 31;

    const uint32_t ctrl = sb + 2 * STAGE_BYTES;
    const uint32_t mb[2] = { sb + 2 * STAGE_BYTES + 8, sb + 2 * STAGE_BYTES + 16 };

    if (tid == 0) { mbar_init(mb[0], 1); mbar_init(mb[1], 1); }
    if (wid == 0) {
        asm volatile("tcgen05.alloc.cta_group::1.sync.aligned.shared::cta.b32 [%0], %1;"
                     :: "r"(ctrl), "r"(256u) : "memory");
        asm volatile("tcgen05.relinquish_alloc_permit.cta_group::1.sync.aligned;");
    }
    __syncthreads();
    uint32_t tmem;
    asm volatile("ld.shared.b32 %0, [%1];" : "=r"(tmem) : "r"(ctrl));

    const __nv_bfloat16* Arow = &g_as[(size_t)m0 * K2];
    const __nv_bfloat16* Brow = &g_bs[((size_t)z * EMB + n0) * K2];

    // per-thread tile coordinates + swizzled store offsets (chunk-invariant)
    const int tr = tid >> 3, tc16 = (tid & 7) * 8;      // row 0..31 base, col seg
    uint32_t offA[4], offB[8];
    #pragma unroll
    for (int j = 0; j < 4; j++)
        offA[j] = sw128((uint32_t)((tr + j * 32) * 128 + tc16 * 2));
    #pragma unroll
    for (int j = 0; j < 8; j++)
        offB[j] = sw128((uint32_t)((tr + j * 32) * 128 + tc16 * 2));

    auto load_chunk = [&](int c, uint4* a, uint4* b) {
        const int kk = c * 64;
        #pragma unroll
        for (int j = 0; j < 4; j++)
            a[j] = *(const uint4*)(Arow + (size_t)(tr + j * 32) * K2 + kk + tc16);
        #pragma unroll
        for (int j = 0; j < 8; j++)
            b[j] = *(const uint4*)(Brow + (size_t)(tr + j * 32) * K2 + kk + tc16);
    };

    int ph[2] = { 0, 0 };
    uint4 ra[4], rb[8];
    load_chunk(0, ra, rb);

    for (int c = 0; c < 36; c++) {
        const int s = c & 1;

        // prefetch chunk c+1 BEFORE the wait — hides LDG latency
        uint4 na[4], nb[8];
        if (c + 1 < 36) load_chunk(c + 1, na, nb);

        if (c >= 2) { mbar_wait(mb[s], ph[s]); ph[s] ^= 1; }
        char* stA = sm + s * STAGE_BYTES;
        char* stB = stA + 16384;
        #pragma unroll
        for (int j = 0; j < 4; j++) *(uint4*)(stA + offA[j]) = ra[j];
        #pragma unroll
        for (int j = 0; j < 8; j++) *(uint4*)(stB + offB[j]) = rb[j];
        asm volatile("fence.proxy.async.shared::cta;" ::: "memory");
        __syncthreads();

        if (wid == 0) {
            if (elect_one()) {
                uint64_t da = make_desc(sb + s * STAGE_BYTES);
                uint64_t db = make_desc(sb + s * STAGE_BYTES + 16384);
                #pragma unroll
                for (int k = 0; k < 4; k++)
                    mma_f16_ss(tmem, da + k * 2, db + k * 2, QKV_IDESC, (c > 0) || (k > 0));
                tc_commit(mb[s]);
            }
        }
        #pragma unroll
        for (int j = 0; j < 4; j++) ra[j] = na[j];
        #pragma unroll
        for (int j = 0; j < 8; j++) rb[j] = nb[j];
    }

    mbar_wait(mb[1], ph[1]);
    asm volatile("tcgen05.fence::after_thread_sync;" ::: "memory");

    if (wid < 4) {
        const int r = wid * 32 + lid;
        #pragma unroll
        for (int cb = 0; cb < 8; cb++) {
            uint32_t dr[32];
            TC_LD_X32(dr, tmem + cb * 32);
            asm volatile("tcgen05.wait::ld.sync.aligned;" ::: "memory");
            const int nbase = n0 + cb * 32;
            const int head = nbase >> 6;
            if (z == 0) {
                float* op = &g_q[((size_t)head * SQ + m0 + r) * HD + (nbase & 63)];
                #pragma unroll
                for (int q = 0; q < 32; q += 4) {
                    float4 v;
                    v.x = (__uint_as_float(dr[q + 0]) + bias[nbase + q + 0]) * 0.125f;
                    v.y = (__uint_as_float(dr[q + 1]) + bias[nbase + q + 1]) * 0.125f;
                    v.z = (__uint_as_float(dr[q + 2]) + bias[nbase + q + 2]) * 0.125f;
                    v.w = (__uint_as_float(dr[q + 3]) + bias[nbase + q + 3]) * 0.125f;
                    *(float4*)&op[q] = v;
                }
            } else if (z == 1) {
                uint32_t hw[16], lw[16];
                #pragma unroll
                for (int q = 0; q < 32; q += 2) {
                    float v0 = __uint_as_float(dr[q + 0]) + bias[nbase + q + 0];
                    float v1 = __uint_as_float(dr[q + 1]) + bias[nbase + q + 1];
                    float h0 = __bfloat162float(__float2bfloat16(v0));
                    float h1 = __bfloat162float(__float2bfloat16(v1));
                    hw[q >> 1] = pack_bf2(h0, h1);
                    lw[q >> 1] = pack_bf2(v0 - h0, v1 - h1);
                }
                size_t base = ((size_t)head * SQ + m0 + r) * HD + (nbase & 63);
                #pragma unroll
                for (int q = 0; q < 4; q++) {
                    *(uint4*)&g_khi[base + q * 8] = *(uint4*)&hw[q * 4];
                    *(uint4*)&g_klo[base + q * 8] = *(uint4*)&lw[q * 4];
                }
            } else {
                #pragma unroll
                for (int q = 0; q < 32; q++) {
                    float v = __uint_as_float(dr[q]) + bias[nbase + q];
                    __nv_bfloat16 hb = __float2bfloat16(v);
                    __nv_bfloat16 lb = __float2bfloat16(v - __bfloat162float(hb));
                    size_t idx = ((size_t)head * HD + (nbase & 63) + q) * SQ + m0 + r;
                    g_vthi[idx] = hb;
                    g_vtlo[idx] = lb;
                }
            }
        }
    }
    __syncthreads();
    if (wid == 0) {
        asm volatile("tcgen05.dealloc.cta_group::1.sync.aligned.b32 %0, %1;"
                     :: "r"(tmem), "r"(256u));
    }
#else
    const int r = tid >> 1;
    const int cb0 = (tid & 1) * 128;
    for (int cc = 0; cc < 128; cc++) {
        const int n = n0 + cb0 + cc;
        const __nv_bfloat16* a = &g_as[(size_t)(m0 + r) * K2];
        const __nv_bfloat16* b = &g_bs[((size_t)z * EMB + n) * K2];
        float acc = 0.0f;
        for (int k = 0; k < K2; k++)
            acc += __bfloat162float(a[k]) * __bfloat162float(b[k]);
        const int head = n >> 6;
        float v = acc + bias[n];
        if (z == 0) {
            g_q[((size_t)head * SQ + m0 + r) * HD + (n & 63)] = v * 0.125f;
        } else if (z == 1) {
            __nv_bfloat16 hb = __float2bfloat16(v);
            __nv_bfloat16 lb = __float2bfloat16(v - __bfloat162float(hb));
            size_t idx = ((size_t)head * SQ + m0 + r) * HD + (n & 63);
            g_khi[idx] = hb; g_klo[idx] = lb;
        } else {
            __nv_bfloat16 hb = __float2bfloat16(v);
            __nv_bfloat16 lb = __float2bfloat16(v - __bfloat162float(hb));
            size_t idx = ((size_t)head * HD + (n & 63)) * SQ + m0 + r;
            g_vthi[idx] = hb; g_vtlo[idx] = lb;
        }
    }
#endif
}

// ---------------------------------------------------------------------------
// Banded attention on tcgen05 (validated R14, unchanged).
// ---------------------------------------------------------------------------
#define AT_QHI   0          // 16KB
#define AT_QLO   16384      // 16KB
#define AT_KHI   32768      // 8KB
#define AT_KLO   40960      // 8KB
#define AT_VTHI  49152      // 8KB
#define AT_VTLO  57344      // 8KB
#define AT_PHI   65536      // 16KB
#define AT_PLO   81920      // 16KB
#define AT_KMSK  98304      // 2 x 64 floats
#define AT_LSUM  98816      // 2 x 128 floats
#define AT_CTRL  99840
#define AT_MBS   99848
#define AT_MBO   99856
#define AT_SMEM  99904
#define ATT_IDESC 0x8100490u   // f32 acc, bf16 a/b, N=64, M=128

__global__ __launch_bounds__(256, 2) void attn_mma_kernel(
    const float* __restrict__ amask,
    const unsigned char* __restrict__ qmask,
    float* __restrict__ out)
{
    const int h  = blockIdx.y;
    const int q0 = blockIdx.x * 128;
    const int tid = threadIdx.x;

#if TC_OK
    extern __shared__ __align__(1024) char sm[];
    const uint32_t sb = smem_u32(sm);
    const int wid = tid >> 5, lane = tid & 31;
    const int wg = wid >> 2;                    // warpgroup 0/1 -> col half
    const int wrow = (wid & 3) * 32 + lane;     // query row 0..127
    const int jc0 = wg * 32;                    // this WG's 32-col window
    const uint32_t mbS = sb + AT_MBS, mbO = sb + AT_MBO;
    float* kmsk = (float*)(sm + AT_KMSK);
    float* lsum = (float*)(sm + AT_LSUM);

    if (tid == 0) { mbar_init(mbS, 1); mbar_init(mbO, 1); }
    if (wid == 0) {
        asm volatile("tcgen05.alloc.cta_group::1.sync.aligned.shared::cta.b32 [%0], %1;"
                     :: "r"(sb + AT_CTRL), "r"(128u) : "memory");
        asm volatile("tcgen05.relinquish_alloc_permit.cta_group::1.sync.aligned;");
    }
    __syncthreads();
    uint32_t tmem;
    asm volatile("ld.shared.b32 %0, [%1];" : "=r"(tmem) : "r"(sb + AT_CTRL));
    const uint32_t TM_S = tmem, TM_O = tmem + 64;

    const int gi = q0 + wrow;

    // per-thread staging coordinates (4 threads per 64-wide row)
    const int rk = tid >> 2, qs = (tid & 3) * 16;
    const uint32_t ko0 = sw128((uint32_t)(rk * 128 + qs * 2));
    const uint32_t ko1 = sw128((uint32_t)(rk * 128 + qs * 2 + 16));

    // ---- Prologue: Q tile -> Qhi/Qlo bf16 swizzled (2 threads per row) ----
    {
        const int r = tid >> 1, hf = (tid & 1) * 32;
        const float* qp = &g_q[((size_t)h * SQ + q0 + r) * HD + hf];
        float f[32];
        #pragma unroll
        for (int i = 0; i < 8; i++) *(float4*)&f[i * 4] = *(const float4*)&qp[i * 4];
        #pragma unroll
        for (int g = 0; g < 4; g++) {
            uint32_t off = sw128((uint32_t)(r * 128 + (hf + g * 8) * 2));
            uint4 hv, lv;
            #pragma unroll
            for (int e = 0; e < 8; e += 2) {
                float x0 = f[g * 8 + e], x1 = f[g * 8 + e + 1];
                float h0 = __bfloat162float(__float2bfloat16(x0));
                float h1 = __bfloat162float(__float2bfloat16(x1));
                ((uint32_t*)&hv)[e >> 1] = pack_bf2(h0, h1);
                ((uint32_t*)&lv)[e >> 1] = pack_bf2(x0 - h0, x1 - h1);
            }
            *(uint4*)(sm + AT_QHI + off) = hv;
            *(uint4*)(sm + AT_QLO + off) = lv;
        }
    }

    // valid band tiles
    int jbs[10]; int nt = 0;
    #pragma unroll
    for (int t = 0; t < 10; t++) {
        int jb = q0 - 256 + t * 64;
        if (jb >= 0 && jb < SQ) jbs[nt++] = jb;
    }

    const uint64_t dQh = make_desc(sb + AT_QHI), dQl = make_desc(sb + AT_QLO);
    const uint64_t dKh = make_desc(sb + AT_KHI), dKl = make_desc(sb + AT_KLO);
    const uint64_t dVh = make_desc(sb + AT_VTHI), dVl = make_desc(sb + AT_VTLO);
    const uint64_t dPh = make_desc(sb + AT_PHI), dPl = make_desc(sb + AT_PLO);

    auto issue_S = [&]() {
        asm volatile("tcgen05.fence::after_thread_sync;" ::: "memory");
        #pragma unroll
        for (int k = 0; k < 4; k++) mma_f16_ss(TM_S, dQh + k * 2, dKh + k * 2, ATT_IDESC, k > 0);
        #pragma unroll
        for (int k = 0; k < 4; k++) mma_f16_ss(TM_S, dQh + k * 2, dKl + k * 2, ATT_IDESC, true);
        #pragma unroll
        for (int k = 0; k < 4; k++) mma_f16_ss(TM_S, dQl + k * 2, dKh + k * 2, ATT_IDESC, true);
        tc_commit(mbS);
    };

    float l_part = 0.0f;
    int phS = 0, phO = 0;

    // ---- Prologue: stage K(0), issue S(0) ----
    {
        const __nv_bfloat16* kh = &g_khi[((size_t)h * SQ + jbs[0] + rk) * HD + qs];
        const __nv_bfloat16* kl = &g_klo[((size_t)h * SQ + jbs[0] + rk) * HD + qs];
        *(uint4*)(sm + AT_KHI + ko0) = *(const uint4*)kh;
        *(uint4*)(sm + AT_KHI + ko1) = *(const uint4*)(kh + 8);
        *(uint4*)(sm + AT_KLO + ko0) = *(const uint4*)kl;
        *(uint4*)(sm + AT_KLO + ko1) = *(const uint4*)(kl + 8);
        if (tid < 64)
            kmsk[tid] = (amask[jbs[0] + tid] != 0.0f) ? -1e8f : 0.0f;
    }
    asm volatile("fence.proxy.async.shared::cta;" ::: "memory");
    __syncthreads();
    if (wid == 0 && elect_one()) issue_S();

    for (int it = 0; it < nt; it++) {
        const int b = it & 1;
        const bool more = (it + 1 < nt);
        const int jb = jbs[it];

        // ---- prefetch K(t+1) + kmsk(t+1) into regs BEFORE the S(t) wait ----
        uint4 ka0, ka1, kb0, kb1;
        float km = 0.0f;
        if (more) {
            const __nv_bfloat16* kh = &g_khi[((size_t)h * SQ + jbs[it + 1] + rk) * HD + qs];
            const __nv_bfloat16* kl = &g_klo[((size_t)h * SQ + jbs[it + 1] + rk) * HD + qs];
            ka0 = *(const uint4*)kh; ka1 = *(const uint4*)(kh + 8);
            kb0 = *(const uint4*)kl; kb1 = *(const uint4*)(kl + 8);
            if (tid < 64)
                km = (amask[jbs[it + 1] + tid] != 0.0f) ? -1e8f : 0.0f;
        }

        // ---- wait S(t), read scores ----
        mbar_wait(mbS, phS); phS ^= 1;
        asm volatile("tcgen05.fence::after_thread_sync;" ::: "memory");
        uint32_t s0[32];
        TC_LD_X32(s0, TM_S + jc0);
        asm volatile("tcgen05.wait::ld.sync.aligned;" ::: "memory");
        asm volatile("tcgen05.fence::before_thread_sync;" ::: "memory");

        // ---- K smem free: store K(t+1), issue S(t+1) (overlaps softmax) ----
        if (more) {
            *(uint4*)(sm + AT_KHI + ko0) = ka0;
            *(uint4*)(sm + AT_KHI + ko1) = ka1;
            *(uint4*)(sm + AT_KLO + ko0) = kb0;
            *(uint4*)(sm + AT_KLO + ko1) = kb1;
            if (tid < 64) kmsk[(b ^ 1) * 64 + tid] = km;
        }
        asm volatile("fence.proxy.async.shared::cta;" ::: "memory");
        __syncthreads();
        if (more && wid == 0 && elect_one()) issue_S();

        // ---- softmax on this WG's 32-col half ----
        float p[32];
        float rs = 0.0f;
        #pragma unroll
        for (int j = 0; j < 32; j++) {
            const int diff = gi - (jb + jc0 + j);
            const bool valid = (diff <= WIN) && (diff >= -WIN);
            float sv = __uint_as_float(s0[j]) + kmsk[b * 64 + jc0 + j];
            float pv = valid ? __expf(sv) : 0.0f;
            p[j] = pv;
            rs += pv;
        }
        l_part += rs;

        // ---- load Vt(t) (pre-split, pre-transposed) ----
        uint4 va0, va1, vb0, vb1;
        {
            const __nv_bfloat16* vh = &g_vthi[((size_t)h * HD + rk) * SQ + jb + qs];
            const __nv_bfloat16* vl = &g_vtlo[((size_t)h * HD + rk) * SQ + jb + qs];
            va0 = *(const uint4*)vh; va1 = *(const uint4*)(vh + 8);
            vb0 = *(const uint4*)vl; vb1 = *(const uint4*)(vl + 8);
        }

        // PV(t-1) must be complete before Vt/P overwrite
        if (it > 0) { mbar_wait(mbO, phO); phO ^= 1; }

        // ---- store Vt ----
        *(uint4*)(sm + AT_VTHI + ko0) = va0;
        *(uint4*)(sm + AT_VTHI + ko1) = va1;
        *(uint4*)(sm + AT_VTLO + ko0) = vb0;
        *(uint4*)(sm + AT_VTLO + ko1) = vb1;

        // ---- store P hi/lo (row wrow, cols jc0..jc0+31) ----
        #pragma unroll
        for (int g = 0; g < 4; g++) {
            uint32_t off = sw128((uint32_t)(wrow * 128 + (jc0 + g * 8) * 2));
            uint4 hv, lv;
            #pragma unroll
            for (int e = 0; e < 8; e += 2) {
                float x0 = p[g * 8 + e], x1 = p[g * 8 + e + 1];
                float h0 = __bfloat162float(__float2bfloat16(x0));
                float h1 = __bfloat162float(__float2bfloat16(x1));
                ((uint32_t*)&hv)[e >> 1] = pack_bf2(h0, h1);
                ((uint32_t*)&lv)[e >> 1] = pack_bf2(x0 - h0, x1 - h1);
            }
            *(uint4*)(sm + AT_PHI + off) = hv;
            *(uint4*)(sm + AT_PLO + off) = lv;
        }
        asm volatile("fence.proxy.async.shared::cta;" ::: "memory");
        __syncthreads();

        // ---- O += P.V (3-term split) ----
        if (wid == 0 && elect_one()) {
            asm volatile("tcgen05.fence::after_thread_sync;" ::: "memory");
            #pragma unroll
            for (int k = 0; k < 4; k++) mma_f16_ss(TM_O, dPh + k * 2, dVh + k * 2, ATT_IDESC, !(it == 0 && k == 0));
            #pragma unroll
            for (int k = 0; k < 4; k++) mma_f16_ss(TM_O, dPh + k * 2, dVl + k * 2, ATT_IDESC, true);
            #pragma unroll
            for (int k = 0; k < 4; k++) mma_f16_ss(TM_O, dPl + k * 2, dVh + k * 2, ATT_IDESC, true);
            tc_commit(mbO);
        }
    }

    // ---- Epilogue: reduce l across WG halves, normalize, write out ----
    lsum[wg * 128 + wrow] = l_part;
    mbar_wait(mbO, phO);
    asm volatile("tcgen05.fence::after_thread_sync;" ::: "memory");
    __syncthreads();
    {
        uint32_t o0[32];
        TC_LD_X32(o0, TM_O + jc0);
        asm volatile("tcgen05.wait::ld.sync.aligned;" ::: "memory");
        const float l_i = lsum[wrow] + lsum[128 + wrow];
        const float inv = (qmask[gi] != 0) ? 0.0f : 1.0f / l_i;
        float* op = &out[(size_t)gi * EMB + h * HD + jc0];
        #pragma unroll
        for (int j = 0; j < 32; j += 4) {
            float4 v;
            v.x = __uint_as_float(o0[j + 0]) * inv;
            v.y = __uint_as_float(o0[j + 1]) * inv;
            v.z = __uint_as_float(o0[j + 2]) * inv;
            v.w = __uint_as_float(o0[j + 3]) * inv;
            *(float4*)&op[j] = v;
        }
    }
    __syncthreads();
    if (wid == 0) {
        asm volatile("tcgen05.dealloc.cta_group::1.sync.aligned.b32 %0, %1;"
                     :: "r"(tmem), "r"(128u));
    }
#else
    // Generic fallback (compute_103 PTX pass only; never runs on GB300).
    if (tid < 128) {
        const int gi = q0 + tid;
        const float* qp = &g_q[((size_t)h * SQ + gi) * HD];
        float l = 0.0f, O[64];
        #pragma unroll
        for (int d = 0; d < 64; d++) O[d] = 0.0f;
        int lo = gi - WIN; if (lo < 0) lo = 0;
        int hi = gi + WIN; if (hi > SQ - 1) hi = SQ - 1;
        for (int gj = lo; gj <= hi; gj++) {
            float s = 0.0f;
            for (int d = 0; d < 64; d++) {
                float kd = __bfloat162float(g_khi[((size_t)h * SQ + gj) * HD + d])
                         + __bfloat162float(g_klo[((size_t)h * SQ + gj) * HD + d]);
                s += qp[d] * kd;
            }
            s += (amask[gj] != 0.0f) ? -1e8f : 0.0f;
            float pv = __expf(s);
            l += pv;
            for (int d = 0; d < 64; d++) {
                float vd = __bfloat162float(g_vthi[((size_t)h * HD + d) * SQ + gj])
                         + __bfloat162float(g_vtlo[((size_t)h * HD + d) * SQ + gj]);
                O[d] += pv * vd;
            }
        }
        const float inv = (qmask[gi] != 0) ? 0.0f : 1.0f / l;
        float* op = &out[(size_t)gi * EMB + h * HD];
        for (int d = 0; d < 64; d++) op[d] = O[d] * inv;
    }
#endif
}

// ---------------------------------------------------------------------------
// Launch
// ---------------------------------------------------------------------------
extern "C" void kernel_launch(void* const* d_in, const int* in_sizes, int n_in,
                              void* d_out, int out_size)
{
    const float* hs            = (const float*)d_in[0];
    const float* amask         = (const float*)d_in[1];
    const unsigned char* qmask = (const unsigned char*)d_in[2];
    const float* Wq = (const float*)d_in[3];
    const float* bq = (const float*)d_in[4];
    const float* Wk = (const float*)d_in[5];
    const float* bk = (const float*)d_in[6];
    const float* Wv = (const float*)d_in[7];
    const float* bv = (const float*)d_in[8];
    float* out = (float*)d_out;

    split_hs_kernel<<<(SQ * EMB / 4) / 256, 256>>>(hs);
    split_w_kernel<<<dim3(EMB / 32, EMB / 32, 3), dim3(32, 32)>>>(Wq, Wk, Wv);

    cudaFuncSetAttribute(qkv_mma_kernel,
                         cudaFuncAttributeMaxDynamicSharedMemorySize, QKV_SMEM);
    qkv_mma_kernel<<<dim3(EMB / 256, SQ / 128, 3), 256, QKV_SMEM>>>(bq, bk, bv);

    cudaFuncSetAttribute(attn_mma_kernel,
                         cudaFuncAttributeMaxDynamicSharedMemorySize, AT_SMEM);
    attn_mma_kernel<<<dim3(SQ / 128, NH), 256, AT_SMEM>>>(amask, qmask, out);
}

// round 16
// speedup vs baseline: 1.8996x; 1.0768x over previous
#include <cuda_runtime.h>
#include <cuda_bf16.h>
#include <math.h>
#include <stdint.h>

// Problem constants
#define SQ   4096
#define EMB  768
#define NH   12
#define HD   64
#define WIN  256
#define K2   2304   // 3 * 768 split-GEMM depth

// Scratch (allocation-free rule: __device__ globals)
__device__ float g_q[NH * SQ * HD];
__device__ __align__(16) __nv_bfloat16 g_khi[NH * SQ * HD];
__device__ __align__(16) __nv_bfloat16 g_klo[NH * SQ * HD];
__device__ __align__(16) __nv_bfloat16 g_vthi[NH * HD * SQ];
__device__ __align__(16) __nv_bfloat16 g_vtlo[NH * HD * SQ];
__device__ __align__(16) __nv_bfloat16 g_as[(size_t)SQ * K2];        // A' [4096][2304] slabs [hi,hi,lo]
__device__ __align__(16) __nv_bfloat16 g_bs[(size_t)3 * EMB * K2];   // B'_z [768 n][2304 k] slabs [hi,lo,hi]

// ---------------------------------------------------------------------------
// PTX helpers — tcgen05 only under the sm_103a feature guard.
// ---------------------------------------------------------------------------
__device__ __forceinline__ uint32_t smem_u32(const void* p) {
    uint32_t a;
    asm("{ .reg .u64 t; cvta.to.shared.u64 t, %1; cvt.u32.u64 %0, t; }" : "=r"(a) : "l"(p));
    return a;
}
__device__ __forceinline__ uint32_t elect_one() {
    uint32_t pred;
    asm volatile("{\n\t.reg .pred p;\n\telect.sync _|p, 0xFFFFFFFF;\n\tselp.b32 %0, 1, 0, p;\n\t}" : "=r"(pred));
    return pred;
}
__device__ __forceinline__ void mbar_init(uint32_t mb, uint32_t cnt) {
    asm volatile("mbarrier.init.shared.b64 [%0], %1;" :: "r"(mb), "r"(cnt) : "memory");
}
__device__ __forceinline__ void mbar_wait(uint32_t mb, uint32_t phase) {
    asm volatile(
        "{\n\t.reg .pred P1;\n\t"
        "WL_%=:\n\t"
        "mbarrier.try_wait.parity.acquire.cta.shared::cta.b64 P1, [%0], %1, 0x989680;\n\t"
        "@P1 bra.uni WD_%=;\n\t"
        "bra.uni WL_%=;\n\t"
        "WD_%=:\n\t}"
        :: "r"(mb), "r"(phase) : "memory");
}

#if defined(__CUDA_ARCH_FEAT_SM103_ALL)
#define TC_OK 1
#else
#define TC_OK 0
#endif

#if TC_OK
__device__ __forceinline__ void mma_f16_ss(uint32_t d, uint64_t a, uint64_t b,
                                           uint32_t idesc, bool acc) {
    uint32_t en = acc ? 1u : 0u;
    asm volatile(
        "{\n\t.reg .pred p;\n\tsetp.ne.u32 p, %5, 0;\n\t"
        "tcgen05.mma.cta_group::1.kind::f16 [%0], %1, %2, %3, {%4, %4, %4, %4}, p;\n\t}"
        :: "r"(d), "l"(a), "l"(b), "r"(idesc), "r"(0u), "r"(en) : "memory");
}
__device__ __forceinline__ void tc_commit(uint32_t mb) {
    asm volatile("tcgen05.commit.cta_group::1.mbarrier::arrive::one.shared::cluster.b64 [%0];"
                 :: "r"(mb) : "memory");
}
#define TC_LD_X32(r, addr) \
    asm volatile( \
        "tcgen05.ld.sync.aligned.32x32b.x32.b32 " \
        "{%0, %1, %2, %3, %4, %5, %6, %7, " \
        " %8, %9, %10, %11, %12, %13, %14, %15, " \
        " %16, %17, %18, %19, %20, %21, %22, %23, " \
        " %24, %25, %26, %27, %28, %29, %30, %31}, [%32];" \
        : "=r"((r)[0]),  "=r"((r)[1]),  "=r"((r)[2]),  "=r"((r)[3]), \
          "=r"((r)[4]),  "=r"((r)[5]),  "=r"((r)[6]),  "=r"((r)[7]), \
          "=r"((r)[8]),  "=r"((r)[9]),  "=r"((r)[10]), "=r"((r)[11]), \
          "=r"((r)[12]), "=r"((r)[13]), "=r"((r)[14]), "=r"((r)[15]), \
          "=r"((r)[16]), "=r"((r)[17]), "=r"((r)[18]), "=r"((r)[19]), \
          "=r"((r)[20]), "=r"((r)[21]), "=r"((r)[22]), "=r"((r)[23]), \
          "=r"((r)[24]), "=r"((r)[25]), "=r"((r)[26]), "=r"((r)[27]), \
          "=r"((r)[28]), "=r"((r)[29]), "=r"((r)[30]), "=r"((r)[31]) \
        : "r"(addr))
#endif

static __device__ __forceinline__ uint64_t make_desc(uint32_t addr) {
    const uint64_t base = (2ull << 61) | (1ull << 46) | (64ull << 32) | (1ull << 16);
    return base | ((uint64_t)(addr >> 4) & 0x3FFF);
}
static __device__ __forceinline__ uint32_t sw128(uint32_t off) {
    return off ^ ((off >> 3) & 0x70);
}
static __device__ __forceinline__ uint32_t pack_bf2(float a, float b) {
    __nv_bfloat162 t = __floats2bfloat162_rn(a, b);
    return *(uint32_t*)&t;
}

// ---------------------------------------------------------------------------
// Split pre-pass: hs -> g_as (slabs hi,hi,lo). Vectorized: 4 elems/thread.
// ---------------------------------------------------------------------------
__global__ void split_hs_kernel(const float* __restrict__ hs)
{
    int i4 = blockIdx.x * 256 + threadIdx.x;       // over (4096*768)/4
    float4 x = ((const float4*)hs)[i4];
    int row = i4 / (EMB / 4), kq = (i4 % (EMB / 4)) * 4;
    float h0 = __bfloat162float(__float2bfloat16(x.x));
    float h1 = __bfloat162float(__float2bfloat16(x.y));
    float h2 = __bfloat162float(__float2bfloat16(x.z));
    float h3 = __bfloat162float(__float2bfloat16(x.w));
    uint2 hv = { pack_bf2(h0, h1), pack_bf2(h2, h3) };
    uint2 lv = { pack_bf2(x.x - h0, x.y - h1), pack_bf2(x.z - h2, x.w - h3) };
    __nv_bfloat16* p = &g_as[(size_t)row * K2];
    *(uint2*)&p[kq] = hv;
    *(uint2*)&p[EMB + kq] = hv;
    *(uint2*)&p[2 * EMB + kq] = lv;
}

__global__ void split_w_kernel(const float* __restrict__ Wq,
                               const float* __restrict__ Wk,
                               const float* __restrict__ Wv)
{
    __shared__ float t[32][33];
    const int z = blockIdx.z;
    const float* W = (z == 0) ? Wq : (z == 1) ? Wk : Wv;
    int k = blockIdx.y * 32 + threadIdx.y;
    int n = blockIdx.x * 32 + threadIdx.x;
    t[threadIdx.y][threadIdx.x] = W[(size_t)k * EMB + n];
    __syncthreads();
    int nn = blockIdx.x * 32 + threadIdx.y;
    int kk = blockIdx.y * 32 + threadIdx.x;
    float x = t[threadIdx.x][threadIdx.y];
    __nv_bfloat16 h = __float2bfloat16(x);
    __nv_bfloat16 l = __float2bfloat16(x - __bfloat162float(h));
    __nv_bfloat16* p = &g_bs[((size_t)z * EMB + nn) * K2];
    p[kk] = h; p[EMB + kk] = l; p[2 * EMB + kk] = h;
}

// ---------------------------------------------------------------------------
// QKV GEMM on tcgen05, M=256 per CTA (2 M-tiles, TMEM D0@0 / D1@256).
// B traffic halves vs M=128. Register-prefetched staging; 2-stage smem.
// grid = (768/256, 4096/256, 3) = (3, 16, 3), block = 256, 1 CTA/SM.
// ---------------------------------------------------------------------------
#define QKV_STAGE 65536                    // A 32KB + B 32KB
#define QKV_SMEM (2 * QKV_STAGE + 32)
#define QKV_IDESC 0x8400490u               // f32 acc, bf16 a/b, N=256, M=128

__global__ __launch_bounds__(256, 1) void qkv_mma_kernel(
    const float* __restrict__ bq, const float* __restrict__ bk,
    const float* __restrict__ bv)
{
    const int z = blockIdx.z;
    const float* bias = (z == 0) ? bq : (z == 1) ? bk : bv;
    const int n0 = blockIdx.x * 256;
    const int m0 = blockIdx.y * 256;
    const int tid = threadIdx.x;

#if TC_OK
    extern __shared__ __align__(1024) char sm[];
    const uint32_t sb = smem_u32(sm);
    const int wid = tid >> 5, lid = tid & 31;

    const uint32_t ctrl = sb + 2 * QKV_STAGE;
    const uint32_t mb[2] = { sb + 2 * QKV_STAGE + 8, sb + 2 * QKV_STAGE + 16 };

    if (tid == 0) { mbar_init(mb[0], 1); mbar_init(mb[1], 1); }
    if (wid == 0) {
        asm volatile("tcgen05.alloc.cta_group::1.sync.aligned.shared::cta.b32 [%0], %1;"
                     :: "r"(ctrl), "r"(512u) : "memory");
        asm volatile("tcgen05.relinquish_alloc_permit.cta_group::1.sync.aligned;");
    }
    __syncthreads();
    uint32_t tmem;
    asm volatile("ld.shared.b32 %0, [%1];" : "=r"(tmem) : "r"(ctrl));
    const uint32_t D0 = tmem, D1 = tmem + 256;

    const __nv_bfloat16* Arow = &g_as[(size_t)m0 * K2];
    const __nv_bfloat16* Brow = &g_bs[((size_t)z * EMB + n0) * K2];

    // per-thread tile coordinates + swizzled store offsets (chunk-invariant)
    const int tr = tid >> 3, tc16 = (tid & 7) * 8;      // base row 0..31, col seg
    uint32_t offR[8];
    #pragma unroll
    for (int j = 0; j < 8; j++)
        offR[j] = sw128((uint32_t)((tr + j * 32) * 128 + tc16 * 2));

    auto load_chunk = [&](int c, uint4* a, uint4* b) {
        const int kk = c * 64;
        #pragma unroll
        for (int j = 0; j < 8; j++)
            a[j] = *(const uint4*)(Arow + (size_t)(tr + j * 32) * K2 + kk + tc16);
        #pragma unroll
        for (int j = 0; j < 8; j++)
            b[j] = *(const uint4*)(Brow + (size_t)(tr + j * 32) * K2 + kk + tc16);
    };

    int ph[2] = { 0, 0 };
    uint4 ra[8], rb[8];
    load_chunk(0, ra, rb);

    for (int c = 0; c < 36; c++) {
        const int s = c & 1;

        // prefetch chunk c+1 BEFORE the wait — hides LDG latency
        uint4 na[8], nb[8];
        if (c + 1 < 36) load_chunk(c + 1, na, nb);

        if (c >= 2) { mbar_wait(mb[s], ph[s]); ph[s] ^= 1; }
        char* stA = sm + s * QKV_STAGE;
        char* stB = stA + 32768;
        #pragma unroll
        for (int j = 0; j < 8; j++) *(uint4*)(stA + offR[j]) = ra[j];
        #pragma unroll
        for (int j = 0; j < 8; j++) *(uint4*)(stB + offR[j]) = rb[j];
        asm volatile("fence.proxy.async.shared::cta;" ::: "memory");
        __syncthreads();

        if (wid == 0) {
            if (elect_one()) {
                uint64_t da0 = make_desc(sb + s * QKV_STAGE);
                uint64_t da1 = make_desc(sb + s * QKV_STAGE + 16384);
                uint64_t db  = make_desc(sb + s * QKV_STAGE + 32768);
                const bool acc = (c > 0);
                #pragma unroll
                for (int k = 0; k < 4; k++)
                    mma_f16_ss(D0, da0 + k * 2, db + k * 2, QKV_IDESC, acc || (k > 0));
                #pragma unroll
                for (int k = 0; k < 4; k++)
                    mma_f16_ss(D1, da1 + k * 2, db + k * 2, QKV_IDESC, acc || (k > 0));
                tc_commit(mb[s]);
            }
        }
        #pragma unroll
        for (int j = 0; j < 8; j++) { ra[j] = na[j]; rb[j] = nb[j]; }
    }

    mbar_wait(mb[1], ph[1]);
    asm volatile("tcgen05.fence::after_thread_sync;" ::: "memory");

    // Epilogue: WG0 reads D0 (rows 0-127), WG1 reads D1 (rows 128-255)
    {
        const uint32_t dbase = (wid < 4) ? D0 : D1;
        const int r = ((wid & 3) * 32 + lid) + ((wid < 4) ? 0 : 128);
        #pragma unroll
        for (int cb = 0; cb < 8; cb++) {
            uint32_t dr[32];
            TC_LD_X32(dr, dbase + cb * 32);
            asm volatile("tcgen05.wait::ld.sync.aligned;" ::: "memory");
            const int nbase = n0 + cb * 32;
            const int head = nbase >> 6;
            if (z == 0) {
                float* op = &g_q[((size_t)head * SQ + m0 + r) * HD + (nbase & 63)];
                #pragma unroll
                for (int q = 0; q < 32; q += 4) {
                    float4 v;
                    v.x = (__uint_as_float(dr[q + 0]) + bias[nbase + q + 0]) * 0.125f;
                    v.y = (__uint_as_float(dr[q + 1]) + bias[nbase + q + 1]) * 0.125f;
                    v.z = (__uint_as_float(dr[q + 2]) + bias[nbase + q + 2]) * 0.125f;
                    v.w = (__uint_as_float(dr[q + 3]) + bias[nbase + q + 3]) * 0.125f;
                    *(float4*)&op[q] = v;
                }
            } else if (z == 1) {
                uint32_t hw[16], lw[16];
                #pragma unroll
                for (int q = 0; q < 32; q += 2) {
                    float v0 = __uint_as_float(dr[q + 0]) + bias[nbase + q + 0];
                    float v1 = __uint_as_float(dr[q + 1]) + bias[nbase + q + 1];
                    float h0 = __bfloat162float(__float2bfloat16(v0));
                    float h1 = __bfloat162float(__float2bfloat16(v1));
                    hw[q >> 1] = pack_bf2(h0, h1);
                    lw[q >> 1] = pack_bf2(v0 - h0, v1 - h1);
                }
                size_t base = ((size_t)head * SQ + m0 + r) * HD + (nbase & 63);
                #pragma unroll
                for (int q = 0; q < 4; q++) {
                    *(uint4*)&g_khi[base + q * 8] = *(uint4*)&hw[q * 4];
                    *(uint4*)&g_klo[base + q * 8] = *(uint4*)&lw[q * 4];
                }
            } else {
                #pragma unroll
                for (int q = 0; q < 32; q++) {
                    float v = __uint_as_float(dr[q]) + bias[nbase + q];
                    __nv_bfloat16 hb = __float2bfloat16(v);
                    __nv_bfloat16 lb = __float2bfloat16(v - __bfloat162float(hb));
                    size_t idx = ((size_t)head * HD + (nbase & 63) + q) * SQ + m0 + r;
                    g_vthi[idx] = hb;
                    g_vtlo[idx] = lb;
                }
            }
        }
    }
    __syncthreads();
    if (wid == 0) {
        asm volatile("tcgen05.dealloc.cta_group::1.sync.aligned.b32 %0, %1;"
                     :: "r"(tmem), "r"(512u));
    }
#else
    // Generic fallback (compute_103 PTX pass only; never runs on GB300).
    for (int rr = 0; rr < 2; rr++) {
        const int r = (tid >> 1) + rr * 128;
        const int cb0 = (tid & 1) * 128;
        for (int cc = 0; cc < 128; cc++) {
            const int n = n0 + cb0 + cc;
            const __nv_bfloat16* a = &g_as[(size_t)(m0 + r) * K2];
            const __nv_bfloat16* b = &g_bs[((size_t)z * EMB + n) * K2];
            float acc = 0.0f;
            for (int k = 0; k < K2; k++)
                acc += __bfloat162float(a[k]) * __bfloat162float(b[k]);
            const int head = n >> 6;
            float v = acc + bias[n];
            if (z == 0) {
                g_q[((size_t)head * SQ + m0 + r) * HD + (n & 63)] = v * 0.125f;
            } else if (z == 1) {
                __nv_bfloat16 hb = __float2bfloat16(v);
                __nv_bfloat16 lb = __float2bfloat16(v - __bfloat162float(hb));
                size_t idx = ((size_t)head * SQ + m0 + r) * HD + (n & 63);
                g_khi[idx] = hb; g_klo[idx] = lb;
            } else {
                __nv_bfloat16 hb = __float2bfloat16(v);
                __nv_bfloat16 lb = __float2bfloat16(v - __bfloat162float(hb));
                size_t idx = ((size_t)head * HD + (n & 63)) * SQ + m0 + r;
                g_vthi[idx] = hb; g_vtlo[idx] = lb;
            }
        }
    }
#endif
}

// ---------------------------------------------------------------------------
// Banded attention on tcgen05 (validated R14/R15, unchanged).
// ---------------------------------------------------------------------------
#define AT_QHI   0          // 16KB
#define AT_QLO   16384      // 16KB
#define AT_KHI   32768      // 8KB
#define AT_KLO   40960      // 8KB
#define AT_VTHI  49152      // 8KB
#define AT_VTLO  57344      // 8KB
#define AT_PHI   65536      // 16KB
#define AT_PLO   81920      // 16KB
#define AT_KMSK  98304      // 2 x 64 floats
#define AT_LSUM  98816      // 2 x 128 floats
#define AT_CTRL  99840
#define AT_MBS   99848
#define AT_MBO   99856
#define AT_SMEM  99904
#define ATT_IDESC 0x8100490u   // f32 acc, bf16 a/b, N=64, M=128

__global__ __launch_bounds__(256, 2) void attn_mma_kernel(
    const float* __restrict__ amask,
    const unsigned char* __restrict__ qmask,
    float* __restrict__ out)
{
    const int h  = blockIdx.y;
    const int q0 = blockIdx.x * 128;
    const int tid = threadIdx.x;

#if TC_OK
    extern __shared__ __align__(1024) char sm[];
    const uint32_t sb = smem_u32(sm);
    const int wid = tid >> 5, lane = tid & 31;
    const int wg = wid >> 2;                    // warpgroup 0/1 -> col half
    const int wrow = (wid & 3) * 32 + lane;     // query row 0..127
    const int jc0 = wg * 32;                    // this WG's 32-col window
    const uint32_t mbS = sb + AT_MBS, mbO = sb + AT_MBO;
    float* kmsk = (float*)(sm + AT_KMSK);
    float* lsum = (float*)(sm + AT_LSUM);

    if (tid == 0) { mbar_init(mbS, 1); mbar_init(mbO, 1); }
    if (wid == 0) {
        asm volatile("tcgen05.alloc.cta_group::1.sync.aligned.shared::cta.b32 [%0], %1;"
                     :: "r"(sb + AT_CTRL), "r"(128u) : "memory");
        asm volatile("tcgen05.relinquish_alloc_permit.cta_group::1.sync.aligned;");
    }
    __syncthreads();
    uint32_t tmem;
    asm volatile("ld.shared.b32 %0, [%1];" : "=r"(tmem) : "r"(sb + AT_CTRL));
    const uint32_t TM_S = tmem, TM_O = tmem + 64;

    const int gi = q0 + wrow;

    // per-thread staging coordinates (4 threads per 64-wide row)
    const int rk = tid >> 2, qs = (tid & 3) * 16;
    const uint32_t ko0 = sw128((uint32_t)(rk * 128 + qs * 2));
    const uint32_t ko1 = sw128((uint32_t)(rk * 128 + qs * 2 + 16));

    // ---- Prologue: Q tile -> Qhi/Qlo bf16 swizzled (2 threads per row) ----
    {
        const int r = tid >> 1, hf = (tid & 1) * 32;
        const float* qp = &g_q[((size_t)h * SQ + q0 + r) * HD + hf];
        float f[32];
        #pragma unroll
        for (int i = 0; i < 8; i++) *(float4*)&f[i * 4] = *(const float4*)&qp[i * 4];
        #pragma unroll
        for (int g = 0; g < 4; g++) {
            uint32_t off = sw128((uint32_t)(r * 128 + (hf + g * 8) * 2));
            uint4 hv, lv;
            #pragma unroll
            for (int e = 0; e < 8; e += 2) {
                float x0 = f[g * 8 + e], x1 = f[g * 8 + e + 1];
                float h0 = __bfloat162float(__float2bfloat16(x0));
                float h1 = __bfloat162float(__float2bfloat16(x1));
                ((uint32_t*)&hv)[e >> 1] = pack_bf2(h0, h1);
                ((uint32_t*)&lv)[e >> 1] = pack_bf2(x0 - h0, x1 - h1);
            }
            *(uint4*)(sm + AT_QHI + off) = hv;
            *(uint4*)(sm + AT_QLO + off) = lv;
        }
    }

    // valid band tiles
    int jbs[10]; int nt = 0;
    #pragma unroll
    for (int t = 0; t < 10; t++) {
        int jb = q0 - 256 + t * 64;
        if (jb >= 0 && jb < SQ) jbs[nt++] = jb;
    }

    const uint64_t dQh = make_desc(sb + AT_QHI), dQl = make_desc(sb + AT_QLO);
    const uint64_t dKh = make_desc(sb + AT_KHI), dKl = make_desc(sb + AT_KLO);
    const uint64_t dVh = make_desc(sb + AT_VTHI), dVl = make_desc(sb + AT_VTLO);
    const uint64_t dPh = make_desc(sb + AT_PHI), dPl = make_desc(sb + AT_PLO);

    auto issue_S = [&]() {
        asm volatile("tcgen05.fence::after_thread_sync;" ::: "memory");
        #pragma unroll
        for (int k = 0; k < 4; k++) mma_f16_ss(TM_S, dQh + k * 2, dKh + k * 2, ATT_IDESC, k > 0);
        #pragma unroll
        for (int k = 0; k < 4; k++) mma_f16_ss(TM_S, dQh + k * 2, dKl + k * 2, ATT_IDESC, true);
        #pragma unroll
        for (int k = 0; k < 4; k++) mma_f16_ss(TM_S, dQl + k * 2, dKh + k * 2, ATT_IDESC, true);
        tc_commit(mbS);
    };

    float l_part = 0.0f;
    int phS = 0, phO = 0;

    // ---- Prologue: stage K(0), issue S(0) ----
    {
        const __nv_bfloat16* kh = &g_khi[((size_t)h * SQ + jbs[0] + rk) * HD + qs];
        const __nv_bfloat16* kl = &g_klo[((size_t)h * SQ + jbs[0] + rk) * HD + qs];
        *(uint4*)(sm + AT_KHI + ko0) = *(const uint4*)kh;
        *(uint4*)(sm + AT_KHI + ko1) = *(const uint4*)(kh + 8);
        *(uint4*)(sm + AT_KLO + ko0) = *(const uint4*)kl;
        *(uint4*)(sm + AT_KLO + ko1) = *(const uint4*)(kl + 8);
        if (tid < 64)
            kmsk[tid] = (amask[jbs[0] + tid] != 0.0f) ? -1e8f : 0.0f;
    }
    asm volatile("fence.proxy.async.shared::cta;" ::: "memory");
    __syncthreads();
    if (wid == 0 && elect_one()) issue_S();

    for (int it = 0; it < nt; it++) {
        const int b = it & 1;
        const bool more = (it + 1 < nt);
        const int jb = jbs[it];

        // ---- prefetch K(t+1) + kmsk(t+1) into regs BEFORE the S(t) wait ----
        uint4 ka0, ka1, kb0, kb1;
        float km = 0.0f;
        if (more) {
            const __nv_bfloat16* kh = &g_khi[((size_t)h * SQ + jbs[it + 1] + rk) * HD + qs];
            const __nv_bfloat16* kl = &g_klo[((size_t)h * SQ + jbs[it + 1] + rk) * HD + qs];
            ka0 = *(const uint4*)kh; ka1 = *(const uint4*)(kh + 8);
            kb0 = *(const uint4*)kl; kb1 = *(const uint4*)(kl + 8);
            if (tid < 64)
                km = (amask[jbs[it + 1] + tid] != 0.0f) ? -1e8f : 0.0f;
        }

        // ---- wait S(t), read scores ----
        mbar_wait(mbS, phS); phS ^= 1;
        asm volatile("tcgen05.fence::after_thread_sync;" ::: "memory");
        uint32_t s0[32];
        TC_LD_X32(s0, TM_S + jc0);
        asm volatile("tcgen05.wait::ld.sync.aligned;" ::: "memory");
        asm volatile("tcgen05.fence::before_thread_sync;" ::: "memory");

        // ---- K smem free: store K(t+1), issue S(t+1) (overlaps softmax) ----
        if (more) {
            *(uint4*)(sm + AT_KHI + ko0) = ka0;
            *(uint4*)(sm + AT_KHI + ko1) = ka1;
            *(uint4*)(sm + AT_KLO + ko0) = kb0;
            *(uint4*)(sm + AT_KLO + ko1) = kb1;
            if (tid < 64) kmsk[(b ^ 1) * 64 + tid] = km;
        }
        asm volatile("fence.proxy.async.shared::cta;" ::: "memory");
        __syncthreads();
        if (more && wid == 0 && elect_one()) issue_S();

        // ---- softmax on this WG's 32-col half ----
        float p[32];
        float rs = 0.0f;
        #pragma unroll
        for (int j = 0; j < 32; j++) {
            const int diff = gi - (jb + jc0 + j);
            const bool valid = (diff <= WIN) && (diff >= -WIN);
            float sv = __uint_as_float(s0[j]) + kmsk[b * 64 + jc0 + j];
            float pv = valid ? __expf(sv) : 0.0f;
            p[j] = pv;
            rs += pv;
        }
        l_part += rs;

        // ---- load Vt(t) (pre-split, pre-transposed) ----
        uint4 va0, va1, vb0, vb1;
        {
            const __nv_bfloat16* vh = &g_vthi[((size_t)h * HD + rk) * SQ + jb + qs];
            const __nv_bfloat16* vl = &g_vtlo[((size_t)h * HD + rk) * SQ + jb + qs];
            va0 = *(const uint4*)vh; va1 = *(const uint4*)(vh + 8);
            vb0 = *(const uint4*)vl; vb1 = *(const uint4*)(vl + 8);
        }

        // PV(t-1) must be complete before Vt/P overwrite
        if (it > 0) { mbar_wait(mbO, phO); phO ^= 1; }

        // ---- store Vt ----
        *(uint4*)(sm + AT_VTHI + ko0) = va0;
        *(uint4*)(sm + AT_VTHI + ko1) = va1;
        *(uint4*)(sm + AT_VTLO + ko0) = vb0;
        *(uint4*)(sm + AT_VTLO + ko1) = vb1;

        // ---- store P hi/lo (row wrow, cols jc0..jc0+31) ----
        #pragma unroll
        for (int g = 0; g < 4; g++) {
            uint32_t off = sw128((uint32_t)(wrow * 128 + (jc0 + g * 8) * 2));
            uint4 hv, lv;
            #pragma unroll
            for (int e = 0; e < 8; e += 2) {
                float x0 = p[g * 8 + e], x1 = p[g * 8 + e + 1];
                float h0 = __bfloat162float(__float2bfloat16(x0));
                float h1 = __bfloat162float(__float2bfloat16(x1));
                ((uint32_t*)&hv)[e >> 1] = pack_bf2(h0, h1);
                ((uint32_t*)&lv)[e >> 1] = pack_bf2(x0 - h0, x1 - h1);
            }
            *(uint4*)(sm + AT_PHI + off) = hv;
            *(uint4*)(sm + AT_PLO + off) = lv;
        }
        asm volatile("fence.proxy.async.shared::cta;" ::: "memory");
        __syncthreads();

        // ---- O += P.V (3-term split) ----
        if (wid == 0 && elect_one()) {
            asm volatile("tcgen05.fence::after_thread_sync;" ::: "memory");
            #pragma unroll
            for (int k = 0; k < 4; k++) mma_f16_ss(TM_O, dPh + k * 2, dVh + k * 2, ATT_IDESC, !(it == 0 && k == 0));
            #pragma unroll
            for (int k = 0; k < 4; k++) mma_f16_ss(TM_O, dPh + k * 2, dVl + k * 2, ATT_IDESC, true);
            #pragma unroll
            for (int k = 0; k < 4; k++) mma_f16_ss(TM_O, dPl + k * 2, dVh + k * 2, ATT_IDESC, true);
            tc_commit(mbO);
        }
    }

    // ---- Epilogue: reduce l across WG halves, normalize, write out ----
    lsum[wg * 128 + wrow] = l_part;
    mbar_wait(mbO, phO);
    asm volatile("tcgen05.fence::after_thread_sync;" ::: "memory");
    __syncthreads();
    {
        uint32_t o0[32];
        TC_LD_X32(o0, TM_O + jc0);
        asm volatile("tcgen05.wait::ld.sync.aligned;" ::: "memory");
        const float l_i = lsum[wrow] + lsum[128 + wrow];
        const float inv = (qmask[gi] != 0) ? 0.0f : 1.0f / l_i;
        float* op = &out[(size_t)gi * EMB + h * HD + jc0];
        #pragma unroll
        for (int j = 0; j < 32; j += 4) {
            float4 v;
            v.x = __uint_as_float(o0[j + 0]) * inv;
            v.y = __uint_as_float(o0[j + 1]) * inv;
            v.z = __uint_as_float(o0[j + 2]) * inv;
            v.w = __uint_as_float(o0[j + 3]) * inv;
            *(float4*)&op[j] = v;
        }
    }
    __syncthreads();
    if (wid == 0) {
        asm volatile("tcgen05.dealloc.cta_group::1.sync.aligned.b32 %0, %1;"
                     :: "r"(tmem), "r"(128u));
    }
#else
    // Generic fallback (compute_103 PTX pass only; never runs on GB300).
    if (tid < 128) {
        const int gi = q0 + tid;
        const float* qp = &g_q[((size_t)h * SQ + gi) * HD];
        float l = 0.0f, O[64];
        #pragma unroll
        for (int d = 0; d < 64; d++) O[d] = 0.0f;
        int lo = gi - WIN; if (lo < 0) lo = 0;
        int hi = gi + WIN; if (hi > SQ - 1) hi = SQ - 1;
        for (int gj = lo; gj <= hi; gj++) {
            float s = 0.0f;
            for (int d = 0; d < 64; d++) {
                float kd = __bfloat162float(g_khi[((size_t)h * SQ + gj) * HD + d])
                         + __bfloat162float(g_klo[((size_t)h * SQ + gj) * HD + d]);
                s += qp[d] * kd;
            }
            s += (amask[gj] != 0.0f) ? -1e8f : 0.0f;
            float pv = __expf(s);
            l += pv;
            for (int d = 0; d < 64; d++) {
                float vd = __bfloat162float(g_vthi[((size_t)h * HD + d) * SQ + gj])
                         + __bfloat162float(g_vtlo[((size_t)h * HD + d) * SQ + gj]);
                O[d] += pv * vd;
            }
        }
        const float inv = (qmask[gi] != 0) ? 0.0f : 1.0f / l;
        float* op = &out[(size_t)gi * EMB + h * HD];
        for (int d = 0; d < 64; d++) op[d] = O[d] * inv;
    }
#endif
}

// ---------------------------------------------------------------------------
// Launch
// ---------------------------------------------------------------------------
extern "C" void kernel_launch(void* const* d_in, const int* in_sizes, int n_in,
                              void* d_out, int out_size)
{
    const float* hs            = (const float*)d_in[0];
    const float* amask         = (const float*)d_in[1];
    const unsigned char* qmask = (const unsigned char*)d_in[2];
    const float* Wq = (const float*)d_in[3];
    const float* bq = (const float*)d_in[4];
    const float* Wk = (const float*)d_in[5];
    const float* bk = (const float*)d_in[6];
    const float* Wv = (const float*)d_in[7];
    const float* bv = (const float*)d_in[8];
    float* out = (float*)d_out;

    split_hs_kernel<<<(SQ * EMB / 4) / 256, 256>>>(hs);
    split_w_kernel<<<dim3(EMB / 32, EMB / 32, 3), dim3(32, 32)>>>(Wq, Wk, Wv);

    cudaFuncSetAttribute(qkv_mma_kernel,
                         cudaFuncAttributeMaxDynamicSharedMemorySize, QKV_SMEM);
    qkv_mma_kernel<<<dim3(EMB / 256, SQ / 256, 3), 256, QKV_SMEM>>>(bq, bk, bv);

    cudaFuncSetAttribute(attn_mma_kernel,
                         cudaFuncAttributeMaxDynamicSharedMemorySize, AT_SMEM);
    attn_mma_kernel<<<dim3(SQ / 128, NH), 256, AT_SMEM>>>(amask, qmask, out);
}